// round 11
// baseline (speedup 1.0000x reference)
#include <cuda_runtime.h>
#include <math.h>
#include <stdint.h>

#define Bc 2
#define Sc 1024
#define Mc 1024
#define Dc 1024
#define Hc 16
#define DHc 64
#define DFFc 4096
#define Stc 2048
#define Zc (Bc*Hc)
#define MEG (1024*1024)
#define Q4 (MEG/4)

// ---------------- scratch (device globals: no allocation allowed) ----------------
__device__ float g_xn [Bc*Sc*Dc];            // exact LN output (residual use)
__device__ float g_xnr[Bc*Sc*Dc];            // tf32-rounded LN output (GEMM use)
__device__ float g_h  [Bc*Stc*Dc];           // concat(mem, xn) rounded
__device__ float g_q  [Zc*Sc*DHc];
__device__ float g_q2 [Zc*Sc*DHc];
__device__ float g_k  [(size_t)Zc*Stc*DHc];
__device__ float g_v  [(size_t)Zc*Stc*DHc];
__device__ float g_vn [(size_t)Zc*Stc*DHc];  // V * invZ
__device__ float g_scb[(size_t)Zc*Sc*Stc];   // raw logits
__device__ uint32_t g_mxu [Zc*Stc];          // column max keys (self)
__device__ uint32_t g_mxu2[Zc*Stc];          // column max keys (cross)
__device__ float g_msc[Zc*Stc];              // column max * scale
__device__ float g_o  [Bc*Sc*Dc];
__device__ float g_tmp[Bc*Sc*Dc];
__device__ float g_out[Bc*Sc*Dc];
__device__ float g_out2[Bc*Sc*Dc];
__device__ float g_ff [(size_t)Bc*Sc*DFFc];
__device__ float g_wts[20*MEG];              // rounded weights/pemb/enc

// offsets into g_wts (floats)
#define OFF_WQ_M   0
#define OFF_WKV_M  (1*MEG)
#define OFF_FCW_M  (3*MEG)
#define OFF_WQ_C   (4*MEG)
#define OFF_WKV_C  (5*MEG)
#define OFF_FCW_C  (7*MEG)
#define OFF_W1     (8*MEG)
#define OFF_W2     (12*MEG)
#define OFF_PEMB   (16*MEG)
#define OFF_ENC    (18*MEG)

// ---------------- helpers ----------------
__device__ __forceinline__ uint32_t f2tf(float f) {
    uint32_t r;
    asm("cvt.rna.tf32.f32 %0, %1;" : "=r"(r) : "f"(f));
    return r;
}
__device__ __forceinline__ float rnd_tf(float f) { return __uint_as_float(f2tf(f)); }

__device__ __forceinline__ uint32_t fkey(float f) {
    uint32_t b = __float_as_uint(f);
    return (b & 0x80000000u) ? ~b : (b | 0x80000000u);
}
__device__ __forceinline__ float funkey(uint32_t k) {
    uint32_t b = (k & 0x80000000u) ? (k & 0x7FFFFFFFu) : ~k;
    return __uint_as_float(b);
}
#define KEY_NEGINF 0x00800000u

__device__ __forceinline__ void cpa16(uint32_t dst, const void* src) {
    asm volatile("cp.async.cg.shared.global [%0], [%1], 16;\n" :: "r"(dst), "l"(src));
}
__device__ __forceinline__ void cpa16z(uint32_t dst, const void* src, int srcbytes) {
    asm volatile("cp.async.cg.shared.global [%0], [%1], 16, %2;\n"
                 :: "r"(dst), "l"(src), "r"(srcbytes));
}
#define CP_COMMIT() asm volatile("cp.async.commit_group;\n")
#define CP_WAIT0()  asm volatile("cp.async.wait_group 0;\n")
#define CP_WAIT1()  asm volatile("cp.async.wait_group 1;\n")
#define CP_WAIT2()  asm volatile("cp.async.wait_group 2;\n")

__device__ __forceinline__ void mma8(float* c, const uint32_t* a, const uint32_t* b) {
    asm volatile(
        "mma.sync.aligned.m16n8k8.row.col.f32.tf32.tf32.f32 "
        "{%0,%1,%2,%3}, {%4,%5,%6,%7}, {%8,%9}, {%0,%1,%2,%3};\n"
        : "+f"(c[0]), "+f"(c[1]), "+f"(c[2]), "+f"(c[3])
        : "r"(a[0]), "r"(a[1]), "r"(a[2]), "r"(a[3]), "r"(b[0]), "r"(b[1]));
}

// ---------------- merged pre-round: all weights + pemb + enc + mem->hcat ----------
__global__ void round_all(
    const float4* __restrict__ wq_m, const float4* __restrict__ wkv_m,
    const float4* __restrict__ fcw_m, const float4* __restrict__ wq_c,
    const float4* __restrict__ wkv_c, const float4* __restrict__ fcw_c,
    const float4* __restrict__ w1, const float4* __restrict__ w2,
    const float4* __restrict__ pemb, const float4* __restrict__ enc,
    const float4* __restrict__ mem, float4* __restrict__ w, float4* __restrict__ hc)
{
    int i = blockIdx.x * 256 + threadIdx.x;          // f4 index, total 22*Q4
    const float4* s;
    float4* d;
    if (i < 20 * Q4) {
        d = w + i;
        if      (i <  1 * Q4) s = wq_m  + i;
        else if (i <  3 * Q4) s = wkv_m + (i -  1 * Q4);
        else if (i <  4 * Q4) s = fcw_m + (i -  3 * Q4);
        else if (i <  5 * Q4) s = wq_c  + (i -  4 * Q4);
        else if (i <  7 * Q4) s = wkv_c + (i -  5 * Q4);
        else if (i <  8 * Q4) s = fcw_c + (i -  7 * Q4);
        else if (i < 12 * Q4) s = w1    + (i -  8 * Q4);
        else if (i < 16 * Q4) s = w2    + (i - 12 * Q4);
        else if (i < 18 * Q4) s = pemb  + (i - 16 * Q4);
        else                  s = enc   + (i - 18 * Q4);
    } else {
        int m = i - 20 * Q4;                         // mem: 2 batches x Q4 f4
        int b = m / Q4;
        int t4 = m - b * Q4;
        s = mem + m;
        d = hc + (size_t)b * (Stc * Dc / 4) + t4;    // hcat top half (t < M)
    }
    float4 v = *s;
    float4 o = { rnd_tf(v.x), rnd_tf(v.y), rnd_tf(v.z), rnd_tf(v.w) };
    *d = o;
}

// ---------------- init both column-max key arrays (once, upfront) ----------------
__global__ void init_mx2(uint32_t* __restrict__ m1, int n1,
                         uint32_t* __restrict__ m2, int n2)
{
    int i = blockIdx.x * 256 + threadIdx.x;
    if (i < n1) m1[i] = KEY_NEGINF;
    if (i < n2) m2[i] = KEY_NEGINF;
}

// ---------------- dense GEMM, cp.async 3-stage, tf32 MMA ----------------
// Tile (MT*32) x 128, 128 threads, 4 warps 2x2; warp tile (MT*16) x 64.
// MT=2 -> 64x128 tile, doubles grid vs 128x128 for better SM coverage.
template<int MT, int ACT, int EPI, int RND>
__global__ void __launch_bounds__(128, 2)
gemm_tf32(const float* __restrict__ A, const float* __restrict__ Bm,
          float* __restrict__ C, float* __restrict__ C2,
          int N, int K, const float* __restrict__ bias, const float* __restrict__ bias2,
          const float* __restrict__ Res, int Sk)
{
    extern __shared__ float sm[];
    constexpr int TM = MT * 32;          // tile rows
    constexpr int ASZ = TM * 36;         // A stage floats
    constexpr int BOFF = 3 * ASZ;        // B base (floats)
    const int tid = threadIdx.x, lane = tid & 31, wid = tid >> 5;
    const int wm = wid & 1, wn = wid >> 1;
    const int lr = lane >> 2, lc = lane & 3;
    const int row0 = blockIdx.y * TM, col0 = blockIdx.x * 128;
    const uint32_t smb = (uint32_t)__cvta_generic_to_shared(sm);

    float acc[MT][8][4];
#pragma unroll
    for (int mt = 0; mt < MT; mt++)
#pragma unroll
        for (int nt = 0; nt < 8; nt++)
#pragma unroll
            for (int e = 0; e < 4; e++) acc[mt][nt][e] = 0.f;

    const int nk = K / 32;
    auto loadAB = [&](int s, int k0) {
#pragma unroll
        for (int it = 0; it < 2 * MT; it++) {
            int lin = tid + it * 128;
            int r = lin >> 3, k4 = (lin & 7) * 4;
            cpa16(smb + (uint32_t)(s * ASZ + r * 36 + k4) * 4,
                  &A[(size_t)(row0 + r) * K + k0 + k4]);
        }
#pragma unroll
        for (int it = 0; it < 8; it++) {
            int lin = tid + it * 128;
            int r = lin >> 5, n4 = (lin & 31) * 4;
            cpa16(smb + (uint32_t)(BOFF + s * 4352 + r * 136 + n4) * 4,
                  &Bm[(size_t)(k0 + r) * N + col0 + n4]);
        }
        CP_COMMIT();
    };

    loadAB(0, 0);
    if (nk > 1) loadAB(1, 32);
    for (int kt = 0; kt < nk; kt++) {
        if (kt + 2 < nk) { loadAB((kt + 2) % 3, (kt + 2) * 32); CP_WAIT2(); }
        else if (kt + 1 < nk) CP_WAIT1();
        else CP_WAIT0();
        __syncthreads();
        const float* As = sm + (kt % 3) * ASZ;
        const float* Bs = sm + BOFF + (kt % 3) * 4352;
#pragma unroll
        for (int k8 = 0; k8 < 32; k8 += 8) {
            uint32_t a[MT][4], b[8][2];
#pragma unroll
            for (int mt = 0; mt < MT; mt++) {
                int r = wm * (MT * 16) + mt * 16 + lr;
                a[mt][0] = __float_as_uint(As[r * 36 + k8 + lc]);
                a[mt][1] = __float_as_uint(As[(r + 8) * 36 + k8 + lc]);
                a[mt][2] = __float_as_uint(As[r * 36 + k8 + lc + 4]);
                a[mt][3] = __float_as_uint(As[(r + 8) * 36 + k8 + lc + 4]);
            }
#pragma unroll
            for (int nt = 0; nt < 8; nt++) {
                int c = wn * 64 + nt * 8 + lr;
                b[nt][0] = __float_as_uint(Bs[(k8 + lc) * 136 + c]);
                b[nt][1] = __float_as_uint(Bs[(k8 + lc + 4) * 136 + c]);
            }
#pragma unroll
            for (int mt = 0; mt < MT; mt++)
#pragma unroll
                for (int nt = 0; nt < 8; nt++)
                    mma8(acc[mt][nt], a[mt], b[nt]);
        }
        __syncthreads();
    }

#pragma unroll
    for (int mt = 0; mt < MT; mt++)
#pragma unroll
        for (int nt = 0; nt < 8; nt++) {
            int r_ = row0 + wm * (MT * 16) + mt * 16 + lr;
            int c_ = col0 + wn * 64 + nt * 8 + 2 * lc;
#pragma unroll
            for (int hf = 0; hf < 2; hf++) {
                int rr = r_ + hf * 8;
                float v0 = acc[mt][nt][hf * 2 + 0];
                float v1 = acc[mt][nt][hf * 2 + 1];
                if (EPI == 0) {
                    if (bias) { v0 += bias[c_]; v1 += bias[c_ + 1]; }
                    if (ACT == 1) {
                        v0 = 0.5f * v0 * (1.0f + erff(v0 * 0.70710678118654752f));
                        v1 = 0.5f * v1 * (1.0f + erff(v1 * 0.70710678118654752f));
                    }
                    if (Res) {
                        v0 += Res[(size_t)rr * N + c_];
                        v1 += Res[(size_t)rr * N + c_ + 1];
                    }
                    if (RND) { v0 = rnd_tf(v0); v1 = rnd_tf(v1); }
                    C[(size_t)rr * N + c_]     = v0;
                    C[(size_t)rr * N + c_ + 1] = v1;
                } else if (EPI == 1) {
                    int b = rr >> 10, i = rr & 1023;
#pragma unroll
                    for (int e = 0; e < 2; e++) {
                        int cc = c_ + e;
                        int h = cc >> 6, d = cc & 63;
                        float val = e ? v1 : v0;
                        size_t dst = (((size_t)(b * Hc + h)) * Sc + i) * DHc + d;
                        C[dst] = rnd_tf(val + (bias ? bias[cc] : 0.f));
                        if (C2) C2[dst] = rnd_tf(val + bias2[cc]);
                    }
                } else { // EPI == 2
                    int b = rr / Sk, j = rr % Sk;
#pragma unroll
                    for (int e = 0; e < 2; e++) {
                        int cc = c_ + e;
                        int isv = cc >> 10;
                        int h = (cc & 1023) >> 6, d = cc & 63;
                        float val = e ? v1 : v0;
                        size_t dst = (((size_t)(b * Hc + h)) * Sk + j) * DHc + d;
                        (isv ? C2 : C)[dst] = rnd_tf(val);
                    }
                }
            }
        }
}

// ---------------- fused QK^T + shifted-pos + mask + column-max atomics ----------
template<int RELS>
__global__ void __launch_bounds__(256, 2)
qk_fused(const float* __restrict__ Q, const float* __restrict__ Q2,
         const float* __restrict__ Kk, const float* __restrict__ PE,
         float* __restrict__ Out, uint32_t* __restrict__ Mxu, int Srows, int Sk)
{
    extern __shared__ float sm[];
    const int tid = threadIdx.x, lane = tid & 31, wid = tid >> 5;
    const int wm = wid & 1, wn = wid >> 1;
    const int lr = lane >> 2, lc = lane & 3;
    const int z = blockIdx.z;
    const int j0 = blockIdx.x * 128, i0 = blockIdx.y * 128;
    const int bb = z >> 4, hh = z & 15;
    const uint32_t smb = (uint32_t)__cvta_generic_to_shared(sm);

    if (RELS && j0 > i0 + 127 + Mc) return;   // fully masked: never read downstream

    float acc[4][4][4];
#pragma unroll
    for (int mt = 0; mt < 4; mt++)
#pragma unroll
        for (int nt = 0; nt < 4; nt++)
#pragma unroll
            for (int e = 0; e < 4; e++) acc[mt][nt][e] = 0.f;

#pragma unroll
    for (int d0 = 0; d0 < DHc; d0 += 32) {
#pragma unroll
        for (int it = 0; it < 4; it++) {
            int lin = tid + it * 256;
            int r = lin >> 3, k4 = (lin & 7) * 4;
            cpa16(smb + (uint32_t)(r * 36 + k4) * 4,
                  &Q[((size_t)z * Srows + i0 + r) * DHc + d0 + k4]);
            cpa16(smb + (uint32_t)(4608 + r * 36 + k4) * 4,
                  &Kk[((size_t)z * Sk + j0 + r) * DHc + d0 + k4]);
            if (RELS) {
                int srcrow = i0 + r + (bb == 0 ? 1 : 0);
                int ok = srcrow < Srows;
                cpa16z(smb + (uint32_t)(9216 + r * 36 + k4) * 4,
                       &Q2[((size_t)z * Srows + (ok ? srcrow : 0)) * DHc + d0 + k4],
                       ok ? 16 : 0);
                cpa16(smb + (uint32_t)(13824 + r * 36 + k4) * 4,
                      &PE[(size_t)(j0 + r) * Dc + hh * DHc + d0 + k4]);
            }
        }
        CP_COMMIT();
        CP_WAIT0();
        __syncthreads();

        const float* Qs  = sm;
        const float* Ks  = sm + 4608;
        const float* Q2s = sm + 9216;
        const float* Ps  = sm + 13824;
#pragma unroll
        for (int k8 = 0; k8 < 32; k8 += 8) {
            uint32_t a[4][4], b[4][2];
#pragma unroll
            for (int mt = 0; mt < 4; mt++) {
                int r = wm * 64 + mt * 16 + lr;
                a[mt][0] = __float_as_uint(Qs[r * 36 + k8 + lc]);
                a[mt][1] = __float_as_uint(Qs[(r + 8) * 36 + k8 + lc]);
                a[mt][2] = __float_as_uint(Qs[r * 36 + k8 + lc + 4]);
                a[mt][3] = __float_as_uint(Qs[(r + 8) * 36 + k8 + lc + 4]);
            }
#pragma unroll
            for (int nt = 0; nt < 4; nt++) {
                int c = wn * 32 + nt * 8 + lr;
                b[nt][0] = __float_as_uint(Ks[c * 36 + k8 + lc]);
                b[nt][1] = __float_as_uint(Ks[c * 36 + k8 + lc + 4]);
            }
#pragma unroll
            for (int mt = 0; mt < 4; mt++)
#pragma unroll
                for (int nt = 0; nt < 4; nt++)
                    mma8(acc[mt][nt], a[mt], b[nt]);
            if (RELS) {
#pragma unroll
                for (int mt = 0; mt < 4; mt++) {
                    int r = wm * 64 + mt * 16 + lr;
                    a[mt][0] = __float_as_uint(Q2s[r * 36 + k8 + lc]);
                    a[mt][1] = __float_as_uint(Q2s[(r + 8) * 36 + k8 + lc]);
                    a[mt][2] = __float_as_uint(Q2s[r * 36 + k8 + lc + 4]);
                    a[mt][3] = __float_as_uint(Q2s[(r + 8) * 36 + k8 + lc + 4]);
                }
#pragma unroll
                for (int nt = 0; nt < 4; nt++) {
                    int c = wn * 32 + nt * 8 + lr;
                    b[nt][0] = __float_as_uint(Ps[c * 36 + k8 + lc]);
                    b[nt][1] = __float_as_uint(Ps[c * 36 + k8 + lc + 4]);
                }
#pragma unroll
                for (int mt = 0; mt < 4; mt++)
#pragma unroll
                    for (int nt = 0; nt < 4; nt++)
                        mma8(acc[mt][nt], a[mt], b[nt]);
            }
        }
        __syncthreads();
    }

    float cmax[4][2];
#pragma unroll
    for (int nt = 0; nt < 4; nt++) { cmax[nt][0] = -3.4e38f; cmax[nt][1] = -3.4e38f; }

#pragma unroll
    for (int mt = 0; mt < 4; mt++)
#pragma unroll
        for (int nt = 0; nt < 4; nt++) {
            int i_ = i0 + wm * 64 + mt * 16 + lr;
            int j_ = j0 + wn * 32 + nt * 8 + 2 * lc;
#pragma unroll
            for (int hf = 0; hf < 2; hf++) {
                int ii = i_ + hf * 8;
#pragma unroll
                for (int e = 0; e < 2; e++) {
                    int jj = j_ + e;
                    float val = acc[mt][nt][hf * 2 + e];
                    if (RELS && jj > ii + Mc) val = -1e30f;   // mask BEFORE scale
                    Out[((size_t)z * Srows + ii) * Sk + jj] = val;
                    cmax[nt][e] = fmaxf(cmax[nt][e], val);
                }
            }
        }

#pragma unroll
    for (int off = 4; off <= 16; off <<= 1)
#pragma unroll
        for (int nt = 0; nt < 4; nt++)
#pragma unroll
            for (int e = 0; e < 2; e++)
                cmax[nt][e] = fmaxf(cmax[nt][e],
                                    __shfl_xor_sync(0xffffffffu, cmax[nt][e], off));
    if (lane < 4) {
#pragma unroll
        for (int nt = 0; nt < 4; nt++)
#pragma unroll
            for (int e = 0; e < 2; e++) {
                int jj = j0 + wn * 32 + nt * 8 + 2 * lc + e;
                atomicMax(&Mxu[(size_t)z * Sk + jj], fkey(cmax[nt][e]));
            }
    }
}

// ---------------- colsumv: read-only column sum-of-exp, write msc + Vn ------------
template<int CAUS>
__global__ void colsumv(const float* __restrict__ P, const uint32_t* __restrict__ Mxu,
                        const float* __restrict__ V, float* __restrict__ Vn,
                        float* __restrict__ Msc, int Srows, int Sk)
{
    __shared__ float red[256];
    __shared__ float izs[128];
    const int z = blockIdx.y;
    const int jl = threadIdx.x & 127;
    const int ty = threadIdx.x >> 7;
    const int j0b = blockIdx.x * 128;
    const int j = j0b + jl;
    const float msc = funkey(Mxu[(size_t)z * Sk + j]) * 0.125f;
    const float* base = P + (size_t)z * Srows * Sk + j;
    const int zend = CAUS ? min(Srows, max(0, j - Mc)) : 0;
    const int i0s = zend + ((ty ^ zend) & 1);   // first i >= zend with i%2 == ty
    float s = 0.f;
#pragma unroll 4
    for (int i = i0s; i < Srows; i += 2)
        s += __expf(base[(size_t)i * Sk] * 0.125f - msc);
    red[threadIdx.x] = s;
    __syncthreads();
    if (ty == 0) {
        izs[jl] = 1.f / (red[jl] + red[jl + 128]);
        Msc[(size_t)z * Sk + j] = msc;
    }
    __syncthreads();
    for (int t = threadIdx.x; t < 128 * 16; t += 256) {
        int row = t >> 4, c4 = (t & 15) * 4;
        float iz = izs[row];
        size_t idx = ((size_t)z * Sk + j0b + row) * DHc + c4;
        float4 v = *(const float4*)&V[idx];
        float4 o = { rnd_tf(v.x * iz), rnd_tf(v.y * iz),
                     rnd_tf(v.z * iz), rnd_tf(v.w * iz) };
        *(float4*)&Vn[idx] = o;
    }
}

// ---------------- AV: on-the-fly exp of raw logits, 2-stage P / 2-stage V ---------
__global__ void __launch_bounds__(256, 2)
av_tf32(const float* __restrict__ P, const float* __restrict__ V,
        const float* __restrict__ Msc, float* __restrict__ O,
        int Srows, int Sk, int caus)
{
    extern __shared__ float sm[];
    const int tid = threadIdx.x, lane = tid & 31, wid = tid >> 5;
    const int wm = wid >> 1, wn = wid & 1;
    const int lr = lane >> 2, lc = lane & 3;
    const int z = blockIdx.y;
    const int i0 = blockIdx.x * 128;
    const int bb = z >> 4, hh = z & 15;
    const uint32_t smb = (uint32_t)__cvta_generic_to_shared(sm);

    float acc[2][4][4];
#pragma unroll
    for (int mt = 0; mt < 2; mt++)
#pragma unroll
        for (int nt = 0; nt < 4; nt++)
#pragma unroll
            for (int e = 0; e < 4; e++) acc[mt][nt][e] = 0.f;

    auto ldP = [&](int j0, float4* pr) {
#pragma unroll
        for (int it = 0; it < 4; it++) {
            int lin = tid + it * 256;
            int r = lin >> 3, jb = (lin & 7) * 4;
            pr[it] = *(const float4*)&P[((size_t)z * Srows + i0 + r) * Sk + j0 + jb];
        }
    };
    auto stP = [&](int s, const float4* pr, int j0) {
#pragma unroll
        for (int it = 0; it < 4; it++) {
            int lin = tid + it * 256;
            int r = lin >> 3, jb = (lin & 7) * 4;
            float4 m4 = *(const float4*)&Msc[(size_t)z * Sk + j0 + jb];
            float4 p;
            p.x = rnd_tf(__expf(pr[it].x * 0.125f - m4.x));
            p.y = rnd_tf(__expf(pr[it].y * 0.125f - m4.y));
            p.z = rnd_tf(__expf(pr[it].z * 0.125f - m4.z));
            p.w = rnd_tf(__expf(pr[it].w * 0.125f - m4.w));
            *(float4*)&sm[s * 4608 + r * 36 + jb] = p;
        }
    };
    auto ldV = [&](int s, int j0) {
#pragma unroll
        for (int it = 0; it < 2; it++) {
            int lin = tid + it * 256;
            int r = lin >> 4, n4 = (lin & 15) * 4;
            cpa16(smb + (uint32_t)(9216 + s * 2304 + r * 72 + n4) * 4,
                  &V[((size_t)z * Sk + j0 + r) * DHc + n4]);
        }
        CP_COMMIT();
    };

    int nk = Sk / 32;
    if (caus) nk = min(nk, (i0 + 127 + Mc) / 32 + 1);   // exp of masked -> 0

    float4 pr[2][4];
    ldP(0, pr[0]);
    ldV(0, 0);
    if (nk > 1) { ldP(32, pr[1]); ldV(1, 32); }
    stP(0, pr[0], 0);
    if (nk > 1) { CP_WAIT1(); } else { CP_WAIT0(); }
    __syncthreads();

    for (int kt = 0; kt < nk; kt++) {
        const float* Ps = sm + (kt & 1) * 4608;
        const float* Vs = sm + 9216 + (kt & 1) * 2304;
#pragma unroll
        for (int k8 = 0; k8 < 32; k8 += 8) {
            uint32_t a[2][4], b[4][2];
#pragma unroll
            for (int mt = 0; mt < 2; mt++) {
                int r = wm * 32 + mt * 16 + lr;
                a[mt][0] = __float_as_uint(Ps[r * 36 + k8 + lc]);
                a[mt][1] = __float_as_uint(Ps[(r + 8) * 36 + k8 + lc]);
                a[mt][2] = __float_as_uint(Ps[r * 36 + k8 + lc + 4]);
                a[mt][3] = __float_as_uint(Ps[(r + 8) * 36 + k8 + lc + 4]);
            }
#pragma unroll
            for (int nt = 0; nt < 4; nt++) {
                int c = wn * 32 + nt * 8 + lr;
                b[nt][0] = __float_as_uint(Vs[(k8 + lc) * 72 + c]);
                b[nt][1] = __float_as_uint(Vs[(k8 + lc + 4) * 72 + c]);
            }
#pragma unroll
            for (int mt = 0; mt < 2; mt++)
#pragma unroll
                for (int nt = 0; nt < 4; nt++)
                    mma8(acc[mt][nt], a[mt], b[nt]);
        }
        if (kt + 1 < nk) {
            __syncthreads();
            stP((kt + 1) & 1, pr[(kt + 1) & 1], (kt + 1) * 32);
            if (kt + 2 < nk) {
                ldP((kt + 2) * 32, pr[kt & 1]);
                ldV(kt & 1, (kt + 2) * 32);
                CP_WAIT1();
            } else {
                CP_WAIT0();
            }
            __syncthreads();
        }
    }

#pragma unroll
    for (int mt = 0; mt < 2; mt++)
#pragma unroll
        for (int nt = 0; nt < 4; nt++) {
            int i_ = i0 + wm * 32 + mt * 16 + lr;
            int d_ = wn * 32 + nt * 8 + 2 * lc;
#pragma unroll
            for (int hf = 0; hf < 2; hf++) {
                int ii = i_ + hf * 8;
                size_t o = ((size_t)(bb * Sc) + ii) * Dc + hh * DHc + d_;
                O[o]     = rnd_tf(acc[mt][nt][hf * 2 + 0]);
                O[o + 1] = rnd_tf(acc[mt][nt][hf * 2 + 1]);
            }
        }
}

// ---------------- LayerNorm ----------------
__global__ void ln_kernel(const float* __restrict__ X, const float* __restrict__ gw,
                          const float* __restrict__ bw, float* __restrict__ Y,
                          float* __restrict__ Yr, float* __restrict__ Yr2,
                          const float* __restrict__ Res)
{
    __shared__ float s1[256], s2[256];
    const int row = blockIdx.x;
    const int tid = threadIdx.x;
    const float* x = X + (size_t)row * Dc;
    float4 v = *(const float4*)&x[tid * 4];
    s1[tid] = v.x + v.y + v.z + v.w;
    s2[tid] = v.x * v.x + v.y * v.y + v.z * v.z + v.w * v.w;
    __syncthreads();
    for (int st = 128; st > 0; st >>= 1) {
        if (tid < st) { s1[tid] += s1[tid + st]; s2[tid] += s2[tid + st]; }
        __syncthreads();
    }
    float mu = s1[0] * (1.f / Dc);
    float var = s2[0] * (1.f / Dc) - mu * mu;
    float rinv = rsqrtf(var + 1e-5f);
    float4 g4 = *(const float4*)&gw[tid * 4];
    float4 b4 = *(const float4*)&bw[tid * 4];
    float4 o;
    o.x = (v.x - mu) * rinv * g4.x + b4.x;
    o.y = (v.y - mu) * rinv * g4.y + b4.y;
    o.z = (v.z - mu) * rinv * g4.z + b4.z;
    o.w = (v.w - mu) * rinv * g4.w + b4.w;
    if (Res) {
        float4 r4 = *(const float4*)&Res[(size_t)row * Dc + tid * 4];
        o.x += r4.x; o.y += r4.y; o.z += r4.z; o.w += r4.w;
    }
    *(float4*)&Y[(size_t)row * Dc + tid * 4] = o;
    if (Yr || Yr2) {
        float4 r = { rnd_tf(o.x), rnd_tf(o.y), rnd_tf(o.z), rnd_tf(o.w) };
        if (Yr) *(float4*)&Yr[(size_t)row * Dc + tid * 4] = r;
        if (Yr2) {
            int b = row >> 10;
            *(float4*)&Yr2[((size_t)(row + (b + 1) * Mc)) * Dc + tid * 4] = r;
        }
    }
}

// ---------------- host-side launcher ----------------
static inline float* sym(const void* s)
{
    void* p = nullptr;
    cudaGetSymbolAddress(&p, s);
    return (float*)p;
}

extern "C" void kernel_launch(void* const* d_in, const int* in_sizes, int n_in,
                              void* d_out, int out_size)
{
    const float* x     = (const float*)d_in[0];
    const float* enc   = (const float*)d_in[1];
    const float* pemb  = (const float*)d_in[2];
    const float* u     = (const float*)d_in[3];
    const float* vvec  = (const float*)d_in[4];
    const float* mem   = (const float*)d_in[5];
    // d_in[6] = tgt_mask — recomputed analytically
    const float* Wq_m  = (const float*)d_in[7];
    const float* Wkv_m = (const float*)d_in[8];
    const float* fcw_m = (const float*)d_in[9];
    const float* fcb_m = (const float*)d_in[10];
    const float* lnm_g = (const float*)d_in[11];
    const float* lnm_b = (const float*)d_in[12];
    const float* Wq_c  = (const float*)d_in[13];
    const float* Wkv_c = (const float*)d_in[14];
    const float* fcw_c = (const float*)d_in[15];
    const float* fcb_c = (const float*)d_in[16];
    const float* lnc_g = (const float*)d_in[17];
    const float* lnc_b = (const float*)d_in[18];
    const float* W1    = (const float*)d_in[19];
    const float* b1    = (const float*)d_in[20];
    const float* W2    = (const float*)d_in[21];
    const float* b2    = (const float*)d_in[22];
    const float* ln1_g = (const float*)d_in[23];
    const float* ln1_b = (const float*)d_in[24];
    const float* ln2_g = (const float*)d_in[25];
    const float* ln2_b = (const float*)d_in[26];
    const float* ln3_g = (const float*)d_in[27];
    const float* ln3_b = (const float*)d_in[28];
    float* out = (float*)d_out;

    float* xn  = sym(g_xn);   float* xnr  = sym(g_xnr); float* hcat = sym(g_h);
    float* q   = sym(g_q);    float* q2   = sym(g_q2);
    float* kk  = sym(g_k);    float* vv   = sym(g_v);   float* vn = sym(g_vn);
    float* scs = sym(g_scb);  float* msc  = sym(g_msc);
    uint32_t* mxu  = (uint32_t*)sym(g_mxu);
    uint32_t* mxu2 = (uint32_t*)sym(g_mxu2);
    float* o   = sym(g_o);    float* tmp  = sym(g_tmp);
    float* o1  = sym(g_out);  float* o2   = sym(g_out2);
    float* ff  = sym(g_ff);   float* w    = sym(g_wts);

    float* wWq_m  = w + OFF_WQ_M;
    float* wWkv_m = w + OFF_WKV_M;
    float* wfcw_m = w + OFF_FCW_M;
    float* wWq_c  = w + OFF_WQ_C;
    float* wWkv_c = w + OFF_WKV_C;
    float* wfcw_c = w + OFF_FCW_C;
    float* wW1    = w + OFF_W1;
    float* wW2    = w + OFF_W2;
    float* wpemb  = w + OFF_PEMB;
    float* wenc   = w + OFF_ENC;

    // smem: TM=64 -> 3*(64*36) + 3*(32*136) floats = 79872 bytes
    const int GSM = 79872;
    cudaFuncSetAttribute(gemm_tf32<2,0,0,0>, cudaFuncAttributeMaxDynamicSharedMemorySize, GSM);
    cudaFuncSetAttribute(gemm_tf32<2,0,1,1>, cudaFuncAttributeMaxDynamicSharedMemorySize, GSM);
    cudaFuncSetAttribute(gemm_tf32<2,0,2,1>, cudaFuncAttributeMaxDynamicSharedMemorySize, GSM);
    cudaFuncSetAttribute(gemm_tf32<2,1,0,1>, cudaFuncAttributeMaxDynamicSharedMemorySize, GSM);
    cudaFuncSetAttribute(qk_fused<1>, cudaFuncAttributeMaxDynamicSharedMemorySize, 73728);
    cudaFuncSetAttribute(qk_fused<0>, cudaFuncAttributeMaxDynamicSharedMemorySize, 73728);
    cudaFuncSetAttribute(av_tf32,     cudaFuncAttributeMaxDynamicSharedMemorySize, 55296);

    const int rowsBS = Bc * Sc;

    // ===== prep: merged pre-round + one-shot max-key init =====
    round_all<<<22 * Q4 / 256, 256>>>(
        (const float4*)Wq_m, (const float4*)Wkv_m, (const float4*)fcw_m,
        (const float4*)Wq_c, (const float4*)Wkv_c, (const float4*)fcw_c,
        (const float4*)W1, (const float4*)W2, (const float4*)pemb,
        (const float4*)enc, (const float4*)mem, (float4*)w, (float4*)hcat);
    init_mx2<<<(Zc * Stc) / 256, 256>>>(mxu, Zc * Stc, mxu2, Zc * Sc);

    // ===== pre-norm 1 (also fills hcat bottom half) =====
    ln_kernel<<<rowsBS, 256>>>(x, ln1_g, ln1_b, xn, xnr, hcat, nullptr);

    // ===== self MHA (Transformer-XL relative attention) =====
    gemm_tf32<2,0,1,1><<<dim3(8, 32), 128, GSM>>>(xnr, wWq_m, q, q2, Dc, Dc, u, vvec, nullptr, Sc);
    gemm_tf32<2,0,2,1><<<dim3(16, 64), 128, GSM>>>(hcat, wWkv_m, kk, vv, 2 * Dc, Dc, nullptr, nullptr, nullptr, Stc);

    qk_fused<1><<<dim3(16, 8, Zc), 256, 73728>>>(q, q2, kk, wpemb, scs, mxu, Sc, Stc);
    colsumv<1><<<dim3(Stc / 128, Zc), 256>>>(scs, mxu, vv, vn, msc, Sc, Stc);
    av_tf32<<<dim3(8, Zc), 256, 55296>>>(scs, vn, msc, o, Sc, Stc, 1);

    gemm_tf32<2,0,0,0><<<dim3(8, 32), 128, GSM>>>(o, wfcw_m, tmp, nullptr, Dc, Dc, fcb_m, nullptr, xn, 0);
    ln_kernel<<<rowsBS, 256>>>(tmp, lnm_g, lnm_b, o1, nullptr, nullptr, x);

    // ===== cross attention =====
    ln_kernel<<<rowsBS, 256>>>(o1, ln2_g, ln2_b, xn, xnr, nullptr, nullptr);
    gemm_tf32<2,0,1,1><<<dim3(8, 32), 128, GSM>>>(xnr, wWq_c, q, nullptr, Dc, Dc, nullptr, nullptr, nullptr, Sc);
    gemm_tf32<2,0,2,1><<<dim3(16, 32), 128, GSM>>>(wenc, wWkv_c, kk, vv, 2 * Dc, Dc, nullptr, nullptr, nullptr, Sc);

    qk_fused<0><<<dim3(8, 8, Zc), 256, 73728>>>(q, nullptr, kk, nullptr, scs, mxu2, Sc, Sc);
    colsumv<0><<<dim3(Sc / 128, Zc), 256>>>(scs, mxu2, vv, vn, msc, Sc, Sc);
    av_tf32<<<dim3(8, Zc), 256, 55296>>>(scs, vn, msc, o, Sc, Sc, 0);

    gemm_tf32<2,0,0,0><<<dim3(8, 32), 128, GSM>>>(o, wfcw_c, tmp, nullptr, Dc, Dc, fcb_c, nullptr, xn, 0);
    ln_kernel<<<rowsBS, 256>>>(tmp, lnc_g, lnc_b, o2, nullptr, nullptr, o1);

    // ===== FFN =====
    ln_kernel<<<rowsBS, 256>>>(o2, ln3_g, ln3_b, xn, xnr, nullptr, nullptr);
    gemm_tf32<2,1,0,1><<<dim3(32, 32), 128, GSM>>>(xnr, wW1, ff, nullptr, DFFc, Dc, b1, nullptr, nullptr, 0);
    gemm_tf32<2,0,0,0><<<dim3(8, 32), 128, GSM>>>(ff, wW2, out, nullptr, Dc, DFFc, b2, nullptr, o2, 0);
}

// round 12
// speedup vs baseline: 1.0681x; 1.0681x over previous
#include <cuda_runtime.h>
#include <math.h>
#include <stdint.h>

#define Bc 2
#define Sc 1024
#define Mc 1024
#define Dc 1024
#define Hc 16
#define DHc 64
#define DFFc 4096
#define Stc 2048
#define Zc (Bc*Hc)
#define MEG (1024*1024)
#define Q4 (MEG/4)

// ---------------- scratch (device globals: no allocation allowed) ----------------
__device__ float g_xn [Bc*Sc*Dc];            // exact LN output (residual use)
__device__ float g_xnr[Bc*Sc*Dc];            // tf32-rounded LN output (GEMM use)
__device__ float g_h  [Bc*Stc*Dc];           // concat(mem, xn) rounded
__device__ float g_q  [Zc*Sc*DHc];
__device__ float g_q2 [Zc*Sc*DHc];
__device__ float g_k  [(size_t)Zc*Stc*DHc];
__device__ float g_v  [(size_t)Zc*Stc*DHc];
__device__ float g_vn [(size_t)Zc*Stc*DHc];  // V * invZ
__device__ float g_scb[(size_t)Zc*Sc*Stc];   // raw logits
__device__ uint32_t g_mxu [Zc*Stc];          // column max keys (self)
__device__ uint32_t g_mxu2[Zc*Stc];          // column max keys (cross)
__device__ float g_msc[Zc*Stc];              // column max * scale
__device__ float g_o  [Bc*Sc*Dc];
__device__ float g_tmp[Bc*Sc*Dc];
__device__ float g_out[Bc*Sc*Dc];
__device__ float g_out2[Bc*Sc*Dc];
__device__ float g_ff [(size_t)Bc*Sc*DFFc];
__device__ float g_wts[20*MEG];              // rounded weights/pemb/enc

// offsets into g_wts (floats)
#define OFF_WQ_M   0
#define OFF_WKV_M  (1*MEG)
#define OFF_FCW_M  (3*MEG)
#define OFF_WQ_C   (4*MEG)
#define OFF_WKV_C  (5*MEG)
#define OFF_FCW_C  (7*MEG)
#define OFF_W1     (8*MEG)
#define OFF_W2     (12*MEG)
#define OFF_PEMB   (16*MEG)
#define OFF_ENC    (18*MEG)

// ---------------- helpers ----------------
__device__ __forceinline__ uint32_t f2tf(float f) {
    uint32_t r;
    asm("cvt.rna.tf32.f32 %0, %1;" : "=r"(r) : "f"(f));
    return r;
}
__device__ __forceinline__ float rnd_tf(float f) { return __uint_as_float(f2tf(f)); }

__device__ __forceinline__ uint32_t fkey(float f) {
    uint32_t b = __float_as_uint(f);
    return (b & 0x80000000u) ? ~b : (b | 0x80000000u);
}
__device__ __forceinline__ float funkey(uint32_t k) {
    uint32_t b = (k & 0x80000000u) ? (k & 0x7FFFFFFFu) : ~k;
    return __uint_as_float(b);
}
#define KEY_NEGINF 0x00800000u

__device__ __forceinline__ void cpa16(uint32_t dst, const void* src) {
    asm volatile("cp.async.cg.shared.global [%0], [%1], 16;\n" :: "r"(dst), "l"(src));
}
__device__ __forceinline__ void cpa16z(uint32_t dst, const void* src, int srcbytes) {
    asm volatile("cp.async.cg.shared.global [%0], [%1], 16, %2;\n"
                 :: "r"(dst), "l"(src), "r"(srcbytes));
}
#define CP_COMMIT() asm volatile("cp.async.commit_group;\n")
#define CP_WAIT0()  asm volatile("cp.async.wait_group 0;\n")
#define CP_WAIT1()  asm volatile("cp.async.wait_group 1;\n")
#define CP_WAIT2()  asm volatile("cp.async.wait_group 2;\n")

__device__ __forceinline__ void mma8(float* c, const uint32_t* a, const uint32_t* b) {
    asm volatile(
        "mma.sync.aligned.m16n8k8.row.col.f32.tf32.tf32.f32 "
        "{%0,%1,%2,%3}, {%4,%5,%6,%7}, {%8,%9}, {%0,%1,%2,%3};\n"
        : "+f"(c[0]), "+f"(c[1]), "+f"(c[2]), "+f"(c[3])
        : "r"(a[0]), "r"(a[1]), "r"(a[2]), "r"(a[3]), "r"(b[0]), "r"(b[1]));
}

// ---------------- merged pre-round: all weights + pemb + enc + mem->hcat ----------
__global__ void round_all(
    const float4* __restrict__ wq_m, const float4* __restrict__ wkv_m,
    const float4* __restrict__ fcw_m, const float4* __restrict__ wq_c,
    const float4* __restrict__ wkv_c, const float4* __restrict__ fcw_c,
    const float4* __restrict__ w1, const float4* __restrict__ w2,
    const float4* __restrict__ pemb, const float4* __restrict__ enc,
    const float4* __restrict__ mem, float4* __restrict__ w, float4* __restrict__ hc)
{
    int i = blockIdx.x * 256 + threadIdx.x;          // f4 index, total 22*Q4
    const float4* s;
    float4* d;
    if (i < 20 * Q4) {
        d = w + i;
        if      (i <  1 * Q4) s = wq_m  + i;
        else if (i <  3 * Q4) s = wkv_m + (i -  1 * Q4);
        else if (i <  4 * Q4) s = fcw_m + (i -  3 * Q4);
        else if (i <  5 * Q4) s = wq_c  + (i -  4 * Q4);
        else if (i <  7 * Q4) s = wkv_c + (i -  5 * Q4);
        else if (i <  8 * Q4) s = fcw_c + (i -  7 * Q4);
        else if (i < 12 * Q4) s = w1    + (i -  8 * Q4);
        else if (i < 16 * Q4) s = w2    + (i - 12 * Q4);
        else if (i < 18 * Q4) s = pemb  + (i - 16 * Q4);
        else                  s = enc   + (i - 18 * Q4);
    } else {
        int m = i - 20 * Q4;                         // mem: 2 batches x Q4 f4
        int b = m / Q4;
        int t4 = m - b * Q4;
        s = mem + m;
        d = hc + (size_t)b * (Stc * Dc / 4) + t4;    // hcat top half (t < M)
    }
    float4 v = *s;
    float4 o = { rnd_tf(v.x), rnd_tf(v.y), rnd_tf(v.z), rnd_tf(v.w) };
    *d = o;
}

// ---------------- init both column-max key arrays (once, upfront) ----------------
__global__ void init_mx2(uint32_t* __restrict__ m1, int n1,
                         uint32_t* __restrict__ m2, int n2)
{
    int i = blockIdx.x * 256 + threadIdx.x;
    if (i < n1) m1[i] = KEY_NEGINF;
    if (i < n2) m2[i] = KEY_NEGINF;
}

// ---------------- dense GEMM, cp.async 2-stage, tf32 MMA, 4 CTAs/SM ----------------
// Tile 64x128, 128 threads, 4 warps 2x2; warp tile 32x64. 16 warps/SM resident.
template<int MT, int ACT, int EPI, int RND>
__global__ void __launch_bounds__(128, 4)
gemm_tf32(const float* __restrict__ A, const float* __restrict__ Bm,
          float* __restrict__ C, float* __restrict__ C2,
          int N, int K, const float* __restrict__ bias, const float* __restrict__ bias2,
          const float* __restrict__ Res, int Sk)
{
    extern __shared__ float sm[];
    constexpr int TM = MT * 32;          // tile rows
    constexpr int ASZ = TM * 36;         // A stage floats
    constexpr int BOFF = 2 * ASZ;        // B base (floats)
    const int tid = threadIdx.x, lane = tid & 31, wid = tid >> 5;
    const int wm = wid & 1, wn = wid >> 1;
    const int lr = lane >> 2, lc = lane & 3;
    const int row0 = blockIdx.y * TM, col0 = blockIdx.x * 128;
    const uint32_t smb = (uint32_t)__cvta_generic_to_shared(sm);

    float acc[MT][8][4];
#pragma unroll
    for (int mt = 0; mt < MT; mt++)
#pragma unroll
        for (int nt = 0; nt < 8; nt++)
#pragma unroll
            for (int e = 0; e < 4; e++) acc[mt][nt][e] = 0.f;

    const int nk = K / 32;
    auto loadAB = [&](int s, int k0) {
#pragma unroll
        for (int it = 0; it < 2 * MT; it++) {
            int lin = tid + it * 128;
            int r = lin >> 3, k4 = (lin & 7) * 4;
            cpa16(smb + (uint32_t)(s * ASZ + r * 36 + k4) * 4,
                  &A[(size_t)(row0 + r) * K + k0 + k4]);
        }
#pragma unroll
        for (int it = 0; it < 8; it++) {
            int lin = tid + it * 128;
            int r = lin >> 5, n4 = (lin & 31) * 4;
            cpa16(smb + (uint32_t)(BOFF + s * 4352 + r * 136 + n4) * 4,
                  &Bm[(size_t)(k0 + r) * N + col0 + n4]);
        }
        CP_COMMIT();
    };

    loadAB(0, 0);
    for (int kt = 0; kt < nk; kt++) {
        if (kt + 1 < nk) { loadAB((kt + 1) & 1, (kt + 1) * 32); CP_WAIT1(); }
        else             { CP_WAIT0(); }
        __syncthreads();
        const float* As = sm + (kt & 1) * ASZ;
        const float* Bs = sm + BOFF + (kt & 1) * 4352;
#pragma unroll
        for (int k8 = 0; k8 < 32; k8 += 8) {
            uint32_t a[MT][4], b[8][2];
#pragma unroll
            for (int mt = 0; mt < MT; mt++) {
                int r = wm * (MT * 16) + mt * 16 + lr;
                a[mt][0] = __float_as_uint(As[r * 36 + k8 + lc]);
                a[mt][1] = __float_as_uint(As[(r + 8) * 36 + k8 + lc]);
                a[mt][2] = __float_as_uint(As[r * 36 + k8 + lc + 4]);
                a[mt][3] = __float_as_uint(As[(r + 8) * 36 + k8 + lc + 4]);
            }
#pragma unroll
            for (int nt = 0; nt < 8; nt++) {
                int c = wn * 64 + nt * 8 + lr;
                b[nt][0] = __float_as_uint(Bs[(k8 + lc) * 136 + c]);
                b[nt][1] = __float_as_uint(Bs[(k8 + lc + 4) * 136 + c]);
            }
#pragma unroll
            for (int mt = 0; mt < MT; mt++)
#pragma unroll
                for (int nt = 0; nt < 8; nt++)
                    mma8(acc[mt][nt], a[mt], b[nt]);
        }
        __syncthreads();
    }

#pragma unroll
    for (int mt = 0; mt < MT; mt++)
#pragma unroll
        for (int nt = 0; nt < 8; nt++) {
            int r_ = row0 + wm * (MT * 16) + mt * 16 + lr;
            int c_ = col0 + wn * 64 + nt * 8 + 2 * lc;
#pragma unroll
            for (int hf = 0; hf < 2; hf++) {
                int rr = r_ + hf * 8;
                float v0 = acc[mt][nt][hf * 2 + 0];
                float v1 = acc[mt][nt][hf * 2 + 1];
                if (EPI == 0) {
                    if (bias) { v0 += bias[c_]; v1 += bias[c_ + 1]; }
                    if (ACT == 1) {
                        v0 = 0.5f * v0 * (1.0f + erff(v0 * 0.70710678118654752f));
                        v1 = 0.5f * v1 * (1.0f + erff(v1 * 0.70710678118654752f));
                    }
                    if (Res) {
                        v0 += Res[(size_t)rr * N + c_];
                        v1 += Res[(size_t)rr * N + c_ + 1];
                    }
                    if (RND) { v0 = rnd_tf(v0); v1 = rnd_tf(v1); }
                    C[(size_t)rr * N + c_]     = v0;
                    C[(size_t)rr * N + c_ + 1] = v1;
                } else if (EPI == 1) {
                    int b = rr >> 10, i = rr & 1023;
#pragma unroll
                    for (int e = 0; e < 2; e++) {
                        int cc = c_ + e;
                        int h = cc >> 6, d = cc & 63;
                        float val = e ? v1 : v0;
                        size_t dst = (((size_t)(b * Hc + h)) * Sc + i) * DHc + d;
                        C[dst] = rnd_tf(val + (bias ? bias[cc] : 0.f));
                        if (C2) C2[dst] = rnd_tf(val + bias2[cc]);
                    }
                } else { // EPI == 2
                    int b = rr / Sk, j = rr % Sk;
#pragma unroll
                    for (int e = 0; e < 2; e++) {
                        int cc = c_ + e;
                        int isv = cc >> 10;
                        int h = (cc & 1023) >> 6, d = cc & 63;
                        float val = e ? v1 : v0;
                        size_t dst = (((size_t)(b * Hc + h)) * Sk + j) * DHc + d;
                        (isv ? C2 : C)[dst] = rnd_tf(val);
                    }
                }
            }
        }
}

// ---------------- fused QK^T + shifted-pos + mask + column-max atomics ----------
template<int RELS>
__global__ void __launch_bounds__(256, 2)
qk_fused(const float* __restrict__ Q, const float* __restrict__ Q2,
         const float* __restrict__ Kk, const float* __restrict__ PE,
         float* __restrict__ Out, uint32_t* __restrict__ Mxu, int Srows, int Sk)
{
    extern __shared__ float sm[];
    const int tid = threadIdx.x, lane = tid & 31, wid = tid >> 5;
    const int wm = wid & 1, wn = wid >> 1;
    const int lr = lane >> 2, lc = lane & 3;
    const int z = blockIdx.z;
    const int j0 = blockIdx.x * 128, i0 = blockIdx.y * 128;
    const int bb = z >> 4, hh = z & 15;
    const uint32_t smb = (uint32_t)__cvta_generic_to_shared(sm);

    if (RELS && j0 > i0 + 127 + Mc) return;   // fully masked: never read downstream

    float acc[4][4][4];
#pragma unroll
    for (int mt = 0; mt < 4; mt++)
#pragma unroll
        for (int nt = 0; nt < 4; nt++)
#pragma unroll
            for (int e = 0; e < 4; e++) acc[mt][nt][e] = 0.f;

#pragma unroll
    for (int d0 = 0; d0 < DHc; d0 += 32) {
#pragma unroll
        for (int it = 0; it < 4; it++) {
            int lin = tid + it * 256;
            int r = lin >> 3, k4 = (lin & 7) * 4;
            cpa16(smb + (uint32_t)(r * 36 + k4) * 4,
                  &Q[((size_t)z * Srows + i0 + r) * DHc + d0 + k4]);
            cpa16(smb + (uint32_t)(4608 + r * 36 + k4) * 4,
                  &Kk[((size_t)z * Sk + j0 + r) * DHc + d0 + k4]);
            if (RELS) {
                int srcrow = i0 + r + (bb == 0 ? 1 : 0);
                int ok = srcrow < Srows;
                cpa16z(smb + (uint32_t)(9216 + r * 36 + k4) * 4,
                       &Q2[((size_t)z * Srows + (ok ? srcrow : 0)) * DHc + d0 + k4],
                       ok ? 16 : 0);
                cpa16(smb + (uint32_t)(13824 + r * 36 + k4) * 4,
                      &PE[(size_t)(j0 + r) * Dc + hh * DHc + d0 + k4]);
            }
        }
        CP_COMMIT();
        CP_WAIT0();
        __syncthreads();

        const float* Qs  = sm;
        const float* Ks  = sm + 4608;
        const float* Q2s = sm + 9216;
        const float* Ps  = sm + 13824;
#pragma unroll
        for (int k8 = 0; k8 < 32; k8 += 8) {
            uint32_t a[4][4], b[4][2];
#pragma unroll
            for (int mt = 0; mt < 4; mt++) {
                int r = wm * 64 + mt * 16 + lr;
                a[mt][0] = __float_as_uint(Qs[r * 36 + k8 + lc]);
                a[mt][1] = __float_as_uint(Qs[(r + 8) * 36 + k8 + lc]);
                a[mt][2] = __float_as_uint(Qs[r * 36 + k8 + lc + 4]);
                a[mt][3] = __float_as_uint(Qs[(r + 8) * 36 + k8 + lc + 4]);
            }
#pragma unroll
            for (int nt = 0; nt < 4; nt++) {
                int c = wn * 32 + nt * 8 + lr;
                b[nt][0] = __float_as_uint(Ks[c * 36 + k8 + lc]);
                b[nt][1] = __float_as_uint(Ks[c * 36 + k8 + lc + 4]);
            }
#pragma unroll
            for (int mt = 0; mt < 4; mt++)
#pragma unroll
                for (int nt = 0; nt < 4; nt++)
                    mma8(acc[mt][nt], a[mt], b[nt]);
            if (RELS) {
#pragma unroll
                for (int mt = 0; mt < 4; mt++) {
                    int r = wm * 64 + mt * 16 + lr;
                    a[mt][0] = __float_as_uint(Q2s[r * 36 + k8 + lc]);
                    a[mt][1] = __float_as_uint(Q2s[(r + 8) * 36 + k8 + lc]);
                    a[mt][2] = __float_as_uint(Q2s[r * 36 + k8 + lc + 4]);
                    a[mt][3] = __float_as_uint(Q2s[(r + 8) * 36 + k8 + lc + 4]);
                }
#pragma unroll
                for (int nt = 0; nt < 4; nt++) {
                    int c = wn * 32 + nt * 8 + lr;
                    b[nt][0] = __float_as_uint(Ps[c * 36 + k8 + lc]);
                    b[nt][1] = __float_as_uint(Ps[c * 36 + k8 + lc + 4]);
                }
#pragma unroll
                for (int mt = 0; mt < 4; mt++)
#pragma unroll
                    for (int nt = 0; nt < 4; nt++)
                        mma8(acc[mt][nt], a[mt], b[nt]);
            }
        }
        __syncthreads();
    }

    float cmax[4][2];
#pragma unroll
    for (int nt = 0; nt < 4; nt++) { cmax[nt][0] = -3.4e38f; cmax[nt][1] = -3.4e38f; }

#pragma unroll
    for (int mt = 0; mt < 4; mt++)
#pragma unroll
        for (int nt = 0; nt < 4; nt++) {
            int i_ = i0 + wm * 64 + mt * 16 + lr;
            int j_ = j0 + wn * 32 + nt * 8 + 2 * lc;
#pragma unroll
            for (int hf = 0; hf < 2; hf++) {
                int ii = i_ + hf * 8;
#pragma unroll
                for (int e = 0; e < 2; e++) {
                    int jj = j_ + e;
                    float val = acc[mt][nt][hf * 2 + e];
                    if (RELS && jj > ii + Mc) val = -1e30f;   // mask BEFORE scale
                    Out[((size_t)z * Srows + ii) * Sk + jj] = val;
                    cmax[nt][e] = fmaxf(cmax[nt][e], val);
                }
            }
        }

#pragma unroll
    for (int off = 4; off <= 16; off <<= 1)
#pragma unroll
        for (int nt = 0; nt < 4; nt++)
#pragma unroll
            for (int e = 0; e < 2; e++)
                cmax[nt][e] = fmaxf(cmax[nt][e],
                                    __shfl_xor_sync(0xffffffffu, cmax[nt][e], off));
    if (lane < 4) {
#pragma unroll
        for (int nt = 0; nt < 4; nt++)
#pragma unroll
            for (int e = 0; e < 2; e++) {
                int jj = j0 + wn * 32 + nt * 8 + 2 * lc + e;
                atomicMax(&Mxu[(size_t)z * Sk + jj], fkey(cmax[nt][e]));
            }
    }
}

// ---------------- colsumv: read-only column sum-of-exp, write msc + Vn ------------
template<int CAUS>
__global__ void colsumv(const float* __restrict__ P, const uint32_t* __restrict__ Mxu,
                        const float* __restrict__ V, float* __restrict__ Vn,
                        float* __restrict__ Msc, int Srows, int Sk)
{
    __shared__ float red[256];
    __shared__ float izs[128];
    const int z = blockIdx.y;
    const int jl = threadIdx.x & 127;
    const int ty = threadIdx.x >> 7;
    const int j0b = blockIdx.x * 128;
    const int j = j0b + jl;
    const float msc = funkey(Mxu[(size_t)z * Sk + j]) * 0.125f;
    const float* base = P + (size_t)z * Srows * Sk + j;
    const int zend = CAUS ? min(Srows, max(0, j - Mc)) : 0;
    const int i0s = zend + ((ty ^ zend) & 1);   // first i >= zend with i%2 == ty
    float s = 0.f;
#pragma unroll 4
    for (int i = i0s; i < Srows; i += 2)
        s += __expf(base[(size_t)i * Sk] * 0.125f - msc);
    red[threadIdx.x] = s;
    __syncthreads();
    if (ty == 0) {
        izs[jl] = 1.f / (red[jl] + red[jl + 128]);
        Msc[(size_t)z * Sk + j] = msc;
    }
    __syncthreads();
    for (int t = threadIdx.x; t < 128 * 16; t += 256) {
        int row = t >> 4, c4 = (t & 15) * 4;
        float iz = izs[row];
        size_t idx = ((size_t)z * Sk + j0b + row) * DHc + c4;
        float4 v = *(const float4*)&V[idx];
        float4 o = { rnd_tf(v.x * iz), rnd_tf(v.y * iz),
                     rnd_tf(v.z * iz), rnd_tf(v.w * iz) };
        *(float4*)&Vn[idx] = o;
    }
}

// ---------------- AV: on-the-fly exp of raw logits, 2-stage P / 2-stage V ---------
__global__ void __launch_bounds__(256, 2)
av_tf32(const float* __restrict__ P, const float* __restrict__ V,
        const float* __restrict__ Msc, float* __restrict__ O,
        int Srows, int Sk, int caus)
{
    extern __shared__ float sm[];
    const int tid = threadIdx.x, lane = tid & 31, wid = tid >> 5;
    const int wm = wid >> 1, wn = wid & 1;
    const int lr = lane >> 2, lc = lane & 3;
    const int z = blockIdx.y;
    const int i0 = blockIdx.x * 128;
    const int bb = z >> 4, hh = z & 15;
    const uint32_t smb = (uint32_t)__cvta_generic_to_shared(sm);

    float acc[2][4][4];
#pragma unroll
    for (int mt = 0; mt < 2; mt++)
#pragma unroll
        for (int nt = 0; nt < 4; nt++)
#pragma unroll
            for (int e = 0; e < 4; e++) acc[mt][nt][e] = 0.f;

    auto ldP = [&](int j0, float4* pr) {
#pragma unroll
        for (int it = 0; it < 4; it++) {
            int lin = tid + it * 256;
            int r = lin >> 3, jb = (lin & 7) * 4;
            pr[it] = *(const float4*)&P[((size_t)z * Srows + i0 + r) * Sk + j0 + jb];
        }
    };
    auto stP = [&](int s, const float4* pr, int j0) {
#pragma unroll
        for (int it = 0; it < 4; it++) {
            int lin = tid + it * 256;
            int r = lin >> 3, jb = (lin & 7) * 4;
            float4 m4 = *(const float4*)&Msc[(size_t)z * Sk + j0 + jb];
            float4 p;
            p.x = rnd_tf(__expf(pr[it].x * 0.125f - m4.x));
            p.y = rnd_tf(__expf(pr[it].y * 0.125f - m4.y));
            p.z = rnd_tf(__expf(pr[it].z * 0.125f - m4.z));
            p.w = rnd_tf(__expf(pr[it].w * 0.125f - m4.w));
            *(float4*)&sm[s * 4608 + r * 36 + jb] = p;
        }
    };
    auto ldV = [&](int s, int j0) {
#pragma unroll
        for (int it = 0; it < 2; it++) {
            int lin = tid + it * 256;
            int r = lin >> 4, n4 = (lin & 15) * 4;
            cpa16(smb + (uint32_t)(9216 + s * 2304 + r * 72 + n4) * 4,
                  &V[((size_t)z * Sk + j0 + r) * DHc + n4]);
        }
        CP_COMMIT();
    };

    int nk = Sk / 32;
    if (caus) nk = min(nk, (i0 + 127 + Mc) / 32 + 1);   // exp of masked -> 0

    float4 pr[2][4];
    ldP(0, pr[0]);
    ldV(0, 0);
    if (nk > 1) { ldP(32, pr[1]); ldV(1, 32); }
    stP(0, pr[0], 0);
    if (nk > 1) { CP_WAIT1(); } else { CP_WAIT0(); }
    __syncthreads();

    for (int kt = 0; kt < nk; kt++) {
        const float* Ps = sm + (kt & 1) * 4608;
        const float* Vs = sm + 9216 + (kt & 1) * 2304;
#pragma unroll
        for (int k8 = 0; k8 < 32; k8 += 8) {
            uint32_t a[2][4], b[4][2];
#pragma unroll
            for (int mt = 0; mt < 2; mt++) {
                int r = wm * 32 + mt * 16 + lr;
                a[mt][0] = __float_as_uint(Ps[r * 36 + k8 + lc]);
                a[mt][1] = __float_as_uint(Ps[(r + 8) * 36 + k8 + lc]);
                a[mt][2] = __float_as_uint(Ps[r * 36 + k8 + lc + 4]);
                a[mt][3] = __float_as_uint(Ps[(r + 8) * 36 + k8 + lc + 4]);
            }
#pragma unroll
            for (int nt = 0; nt < 4; nt++) {
                int c = wn * 32 + nt * 8 + lr;
                b[nt][0] = __float_as_uint(Vs[(k8 + lc) * 72 + c]);
                b[nt][1] = __float_as_uint(Vs[(k8 + lc + 4) * 72 + c]);
            }
#pragma unroll
            for (int mt = 0; mt < 2; mt++)
#pragma unroll
                for (int nt = 0; nt < 4; nt++)
                    mma8(acc[mt][nt], a[mt], b[nt]);
        }
        if (kt + 1 < nk) {
            __syncthreads();
            stP((kt + 1) & 1, pr[(kt + 1) & 1], (kt + 1) * 32);
            if (kt + 2 < nk) {
                ldP((kt + 2) * 32, pr[kt & 1]);
                ldV(kt & 1, (kt + 2) * 32);
                CP_WAIT1();
            } else {
                CP_WAIT0();
            }
            __syncthreads();
        }
    }

#pragma unroll
    for (int mt = 0; mt < 2; mt++)
#pragma unroll
        for (int nt = 0; nt < 4; nt++) {
            int i_ = i0 + wm * 32 + mt * 16 + lr;
            int d_ = wn * 32 + nt * 8 + 2 * lc;
#pragma unroll
            for (int hf = 0; hf < 2; hf++) {
                int ii = i_ + hf * 8;
                size_t o = ((size_t)(bb * Sc) + ii) * Dc + hh * DHc + d_;
                O[o]     = rnd_tf(acc[mt][nt][hf * 2 + 0]);
                O[o + 1] = rnd_tf(acc[mt][nt][hf * 2 + 1]);
            }
        }
}

// ---------------- LayerNorm ----------------
__global__ void ln_kernel(const float* __restrict__ X, const float* __restrict__ gw,
                          const float* __restrict__ bw, float* __restrict__ Y,
                          float* __restrict__ Yr, float* __restrict__ Yr2,
                          const float* __restrict__ Res)
{
    __shared__ float s1[256], s2[256];
    const int row = blockIdx.x;
    const int tid = threadIdx.x;
    const float* x = X + (size_t)row * Dc;
    float4 v = *(const float4*)&x[tid * 4];
    s1[tid] = v.x + v.y + v.z + v.w;
    s2[tid] = v.x * v.x + v.y * v.y + v.z * v.z + v.w * v.w;
    __syncthreads();
    for (int st = 128; st > 0; st >>= 1) {
        if (tid < st) { s1[tid] += s1[tid + st]; s2[tid] += s2[tid + st]; }
        __syncthreads();
    }
    float mu = s1[0] * (1.f / Dc);
    float var = s2[0] * (1.f / Dc) - mu * mu;
    float rinv = rsqrtf(var + 1e-5f);
    float4 g4 = *(const float4*)&gw[tid * 4];
    float4 b4 = *(const float4*)&bw[tid * 4];
    float4 o;
    o.x = (v.x - mu) * rinv * g4.x + b4.x;
    o.y = (v.y - mu) * rinv * g4.y + b4.y;
    o.z = (v.z - mu) * rinv * g4.z + b4.z;
    o.w = (v.w - mu) * rinv * g4.w + b4.w;
    if (Res) {
        float4 r4 = *(const float4*)&Res[(size_t)row * Dc + tid * 4];
        o.x += r4.x; o.y += r4.y; o.z += r4.z; o.w += r4.w;
    }
    *(float4*)&Y[(size_t)row * Dc + tid * 4] = o;
    if (Yr || Yr2) {
        float4 r = { rnd_tf(o.x), rnd_tf(o.y), rnd_tf(o.z), rnd_tf(o.w) };
        if (Yr) *(float4*)&Yr[(size_t)row * Dc + tid * 4] = r;
        if (Yr2) {
            int b = row >> 10;
            *(float4*)&Yr2[((size_t)(row + (b + 1) * Mc)) * Dc + tid * 4] = r;
        }
    }
}

// ---------------- host-side launcher ----------------
static inline float* sym(const void* s)
{
    void* p = nullptr;
    cudaGetSymbolAddress(&p, s);
    return (float*)p;
}

extern "C" void kernel_launch(void* const* d_in, const int* in_sizes, int n_in,
                              void* d_out, int out_size)
{
    const float* x     = (const float*)d_in[0];
    const float* enc   = (const float*)d_in[1];
    const float* pemb  = (const float*)d_in[2];
    const float* u     = (const float*)d_in[3];
    const float* vvec  = (const float*)d_in[4];
    const float* mem   = (const float*)d_in[5];
    // d_in[6] = tgt_mask — recomputed analytically
    const float* Wq_m  = (const float*)d_in[7];
    const float* Wkv_m = (const float*)d_in[8];
    const float* fcw_m = (const float*)d_in[9];
    const float* fcb_m = (const float*)d_in[10];
    const float* lnm_g = (const float*)d_in[11];
    const float* lnm_b = (const float*)d_in[12];
    const float* Wq_c  = (const float*)d_in[13];
    const float* Wkv_c = (const float*)d_in[14];
    const float* fcw_c = (const float*)d_in[15];
    const float* fcb_c = (const float*)d_in[16];
    const float* lnc_g = (const float*)d_in[17];
    const float* lnc_b = (const float*)d_in[18];
    const float* W1    = (const float*)d_in[19];
    const float* b1    = (const float*)d_in[20];
    const float* W2    = (const float*)d_in[21];
    const float* b2    = (const float*)d_in[22];
    const float* ln1_g = (const float*)d_in[23];
    const float* ln1_b = (const float*)d_in[24];
    const float* ln2_g = (const float*)d_in[25];
    const float* ln2_b = (const float*)d_in[26];
    const float* ln3_g = (const float*)d_in[27];
    const float* ln3_b = (const float*)d_in[28];
    float* out = (float*)d_out;

    float* xn  = sym(g_xn);   float* xnr  = sym(g_xnr); float* hcat = sym(g_h);
    float* q   = sym(g_q);    float* q2   = sym(g_q2);
    float* kk  = sym(g_k);    float* vv   = sym(g_v);   float* vn = sym(g_vn);
    float* scs = sym(g_scb);  float* msc  = sym(g_msc);
    uint32_t* mxu  = (uint32_t*)sym(g_mxu);
    uint32_t* mxu2 = (uint32_t*)sym(g_mxu2);
    float* o   = sym(g_o);    float* tmp  = sym(g_tmp);
    float* o1  = sym(g_out);  float* o2   = sym(g_out2);
    float* ff  = sym(g_ff);   float* w    = sym(g_wts);

    float* wWq_m  = w + OFF_WQ_M;
    float* wWkv_m = w + OFF_WKV_M;
    float* wfcw_m = w + OFF_FCW_M;
    float* wWq_c  = w + OFF_WQ_C;
    float* wWkv_c = w + OFF_WKV_C;
    float* wfcw_c = w + OFF_FCW_C;
    float* wW1    = w + OFF_W1;
    float* wW2    = w + OFF_W2;
    float* wpemb  = w + OFF_PEMB;
    float* wenc   = w + OFF_ENC;

    // smem: TM=64, 2-stage -> 2*(64*36 + 32*136)*4 = 53248 bytes (4 CTAs/SM)
    const int GSM = 53248;
    cudaFuncSetAttribute(gemm_tf32<2,0,0,0>, cudaFuncAttributeMaxDynamicSharedMemorySize, GSM);
    cudaFuncSetAttribute(gemm_tf32<2,0,1,1>, cudaFuncAttributeMaxDynamicSharedMemorySize, GSM);
    cudaFuncSetAttribute(gemm_tf32<2,0,2,1>, cudaFuncAttributeMaxDynamicSharedMemorySize, GSM);
    cudaFuncSetAttribute(gemm_tf32<2,1,0,1>, cudaFuncAttributeMaxDynamicSharedMemorySize, GSM);
    cudaFuncSetAttribute(qk_fused<1>, cudaFuncAttributeMaxDynamicSharedMemorySize, 73728);
    cudaFuncSetAttribute(qk_fused<0>, cudaFuncAttributeMaxDynamicSharedMemorySize, 73728);
    cudaFuncSetAttribute(av_tf32,     cudaFuncAttributeMaxDynamicSharedMemorySize, 55296);

    const int rowsBS = Bc * Sc;

    // ===== prep: merged pre-round + one-shot max-key init =====
    round_all<<<22 * Q4 / 256, 256>>>(
        (const float4*)Wq_m, (const float4*)Wkv_m, (const float4*)fcw_m,
        (const float4*)Wq_c, (const float4*)Wkv_c, (const float4*)fcw_c,
        (const float4*)W1, (const float4*)W2, (const float4*)pemb,
        (const float4*)enc, (const float4*)mem, (float4*)w, (float4*)hcat);
    init_mx2<<<(Zc * Stc) / 256, 256>>>(mxu, Zc * Stc, mxu2, Zc * Sc);

    // ===== pre-norm 1 (also fills hcat bottom half) =====
    ln_kernel<<<rowsBS, 256>>>(x, ln1_g, ln1_b, xn, xnr, hcat, nullptr);

    // ===== self MHA (Transformer-XL relative attention) =====
    gemm_tf32<2,0,1,1><<<dim3(8, 32), 128, GSM>>>(xnr, wWq_m, q, q2, Dc, Dc, u, vvec, nullptr, Sc);
    gemm_tf32<2,0,2,1><<<dim3(16, 64), 128, GSM>>>(hcat, wWkv_m, kk, vv, 2 * Dc, Dc, nullptr, nullptr, nullptr, Stc);

    qk_fused<1><<<dim3(16, 8, Zc), 256, 73728>>>(q, q2, kk, wpemb, scs, mxu, Sc, Stc);
    colsumv<1><<<dim3(Stc / 128, Zc), 256>>>(scs, mxu, vv, vn, msc, Sc, Stc);
    av_tf32<<<dim3(8, Zc), 256, 55296>>>(scs, vn, msc, o, Sc, Stc, 1);

    gemm_tf32<2,0,0,0><<<dim3(8, 32), 128, GSM>>>(o, wfcw_m, tmp, nullptr, Dc, Dc, fcb_m, nullptr, xn, 0);
    ln_kernel<<<rowsBS, 256>>>(tmp, lnm_g, lnm_b, o1, nullptr, nullptr, x);

    // ===== cross attention =====
    ln_kernel<<<rowsBS, 256>>>(o1, ln2_g, ln2_b, xn, xnr, nullptr, nullptr);
    gemm_tf32<2,0,1,1><<<dim3(8, 32), 128, GSM>>>(xnr, wWq_c, q, nullptr, Dc, Dc, nullptr, nullptr, nullptr, Sc);
    gemm_tf32<2,0,2,1><<<dim3(16, 32), 128, GSM>>>(wenc, wWkv_c, kk, vv, 2 * Dc, Dc, nullptr, nullptr, nullptr, Sc);

    qk_fused<0><<<dim3(8, 8, Zc), 256, 73728>>>(q, nullptr, kk, nullptr, scs, mxu2, Sc, Sc);
    colsumv<0><<<dim3(Sc / 128, Zc), 256>>>(scs, mxu2, vv, vn, msc, Sc, Sc);
    av_tf32<<<dim3(8, Zc), 256, 55296>>>(scs, vn, msc, o, Sc, Sc, 0);

    gemm_tf32<2,0,0,0><<<dim3(8, 32), 128, GSM>>>(o, wfcw_c, tmp, nullptr, Dc, Dc, fcb_c, nullptr, xn, 0);
    ln_kernel<<<rowsBS, 256>>>(tmp, lnc_g, lnc_b, o2, nullptr, nullptr, o1);

    // ===== FFN =====
    ln_kernel<<<rowsBS, 256>>>(o2, ln3_g, ln3_b, xn, xnr, nullptr, nullptr);
    gemm_tf32<2,1,0,1><<<dim3(32, 32), 128, GSM>>>(xnr, wW1, ff, nullptr, DFFc, Dc, b1, nullptr, nullptr, 0);
    gemm_tf32<2,0,0,0><<<dim3(8, 32), 128, GSM>>>(ff, wW2, out, nullptr, Dc, DFFc, b2, nullptr, o2, 0);
}

// round 14
// speedup vs baseline: 1.0715x; 1.0032x over previous
#include <cuda_runtime.h>
#include <math.h>
#include <stdint.h>

#define Bc 2
#define Sc 1024
#define Mc 1024
#define Dc 1024
#define Hc 16
#define DHc 64
#define DFFc 4096
#define Stc 2048
#define Zc (Bc*Hc)
#define MEG (1024*1024)
#define Q4 (MEG/4)

// ---------------- scratch (device globals: no allocation allowed) ----------------
__device__ float g_xn [Bc*Sc*Dc];
__device__ float g_xnr[Bc*Sc*Dc];
__device__ float g_h  [Bc*Stc*Dc];
__device__ float g_q  [Zc*Sc*DHc];
__device__ float g_q2 [Zc*Sc*DHc];
__device__ float g_k  [(size_t)Zc*Stc*DHc];
__device__ float g_v  [(size_t)Zc*Stc*DHc];
__device__ float g_vn [(size_t)Zc*Stc*DHc];
__device__ float g_scb[(size_t)Zc*Sc*Stc];
__device__ uint32_t g_mxu [Zc*Stc];
__device__ uint32_t g_mxu2[Zc*Stc];
__device__ float g_msc[Zc*Stc];
__device__ float g_o  [Bc*Sc*Dc];
__device__ float g_tmp[Bc*Sc*Dc];
__device__ float g_out[Bc*Sc*Dc];
__device__ float g_out2[Bc*Sc*Dc];
__device__ float g_ff [(size_t)Bc*Sc*DFFc];
__device__ float g_wts[20*MEG];

#define OFF_WQ_M   0
#define OFF_WKV_M  (1*MEG)
#define OFF_FCW_M  (3*MEG)
#define OFF_WQ_C   (4*MEG)
#define OFF_WKV_C  (5*MEG)
#define OFF_FCW_C  (7*MEG)
#define OFF_W1     (8*MEG)
#define OFF_W2     (12*MEG)
#define OFF_PEMB   (16*MEG)
#define OFF_ENC    (18*MEG)

// ---------------- helpers ----------------
__device__ __forceinline__ uint32_t f2tf(float f) {
    uint32_t r;
    asm("cvt.rna.tf32.f32 %0, %1;" : "=r"(r) : "f"(f));
    return r;
}
__device__ __forceinline__ float rnd_tf(float f) { return __uint_as_float(f2tf(f)); }

__device__ __forceinline__ uint32_t fkey(float f) {
    uint32_t b = __float_as_uint(f);
    return (b & 0x80000000u) ? ~b : (b | 0x80000000u);
}
__device__ __forceinline__ float funkey(uint32_t k) {
    uint32_t b = (k & 0x80000000u) ? (k & 0x7FFFFFFFu) : ~k;
    return __uint_as_float(b);
}
#define KEY_NEGINF 0x00800000u

__device__ __forceinline__ void cpa16(uint32_t dst, const void* src) {
    asm volatile("cp.async.cg.shared.global [%0], [%1], 16;\n" :: "r"(dst), "l"(src));
}
__device__ __forceinline__ void cpa16z(uint32_t dst, const void* src, int srcbytes) {
    asm volatile("cp.async.cg.shared.global [%0], [%1], 16, %2;\n"
                 :: "r"(dst), "l"(src), "r"(srcbytes));
}
#define CP_COMMIT() asm volatile("cp.async.commit_group;\n")
#define CP_WAIT0()  asm volatile("cp.async.wait_group 0;\n")
#define CP_WAIT1()  asm volatile("cp.async.wait_group 1;\n")

__device__ __forceinline__ void mma8(float* c, const uint32_t* a, const uint32_t* b) {
    asm volatile(
        "mma.sync.aligned.m16n8k8.row.col.f32.tf32.tf32.f32 "
        "{%0,%1,%2,%3}, {%4,%5,%6,%7}, {%8,%9}, {%0,%1,%2,%3};\n"
        : "+f"(c[0]), "+f"(c[1]), "+f"(c[2]), "+f"(c[3])
        : "r"(a[0]), "r"(a[1]), "r"(a[2]), "r"(a[3]), "r"(b[0]), "r"(b[1]));
}

// ---------------- merged pre-round + max-key init ----------------
__global__ void round_all(
    const float4* __restrict__ wq_m, const float4* __restrict__ wkv_m,
    const float4* __restrict__ fcw_m, const float4* __restrict__ wq_c,
    const float4* __restrict__ wkv_c, const float4* __restrict__ fcw_c,
    const float4* __restrict__ w1, const float4* __restrict__ w2,
    const float4* __restrict__ pemb, const float4* __restrict__ enc,
    const float4* __restrict__ mem, float4* __restrict__ w, float4* __restrict__ hc,
    uint32_t* __restrict__ mxu, uint32_t* __restrict__ mxu2)
{
    int i = blockIdx.x * 256 + threadIdx.x;          // [0, 22*Q4 + 98304)
    if (i >= 22 * Q4) {
        int k = i - 22 * Q4;                         // init max keys
        if (k < Zc * Stc) mxu[k] = KEY_NEGINF;
        else              mxu2[k - Zc * Stc] = KEY_NEGINF;
        return;
    }
    const float4* s;
    float4* d;
    if (i < 20 * Q4) {
        d = w + i;
        if      (i <  1 * Q4) s = wq_m  + i;
        else if (i <  3 * Q4) s = wkv_m + (i -  1 * Q4);
        else if (i <  4 * Q4) s = fcw_m + (i -  3 * Q4);
        else if (i <  5 * Q4) s = wq_c  + (i -  4 * Q4);
        else if (i <  7 * Q4) s = wkv_c + (i -  5 * Q4);
        else if (i <  8 * Q4) s = fcw_c + (i -  7 * Q4);
        else if (i < 12 * Q4) s = w1    + (i -  8 * Q4);
        else if (i < 16 * Q4) s = w2    + (i - 12 * Q4);
        else if (i < 18 * Q4) s = pemb  + (i - 16 * Q4);
        else                  s = enc   + (i - 18 * Q4);
    } else {
        int m = i - 20 * Q4;
        int b = m / Q4;
        int t4 = m - b * Q4;
        s = mem + m;
        d = hc + (size_t)b * (Stc * Dc / 4) + t4;
    }
    float4 v = *s;
    float4 o = { rnd_tf(v.x), rnd_tf(v.y), rnd_tf(v.z), rnd_tf(v.w) };
    *d = o;
}

// ---------------- dense GEMM body (device fn), 64x128 tile, 2-stage ----------------
template<int MT, int ACT, int EPI, int RND>
__device__ __forceinline__ void gemm_body(
    int bx, int by, float* sm,
    const float* __restrict__ A, const float* __restrict__ Bm,
    float* __restrict__ C, float* __restrict__ C2,
    int N, int K, const float* __restrict__ bias, const float* __restrict__ bias2,
    const float* __restrict__ Res, int Sk)
{
    constexpr int TM = MT * 32;
    constexpr int ASZ = TM * 36;
    constexpr int BOFF = 2 * ASZ;
    const int tid = threadIdx.x, lane = tid & 31, wid = tid >> 5;
    const int wm = wid & 1, wn = wid >> 1;
    const int lr = lane >> 2, lc = lane & 3;
    const int row0 = by * TM, col0 = bx * 128;
    const uint32_t smb = (uint32_t)__cvta_generic_to_shared(sm);

    float acc[MT][8][4];
#pragma unroll
    for (int mt = 0; mt < MT; mt++)
#pragma unroll
        for (int nt = 0; nt < 8; nt++)
#pragma unroll
            for (int e = 0; e < 4; e++) acc[mt][nt][e] = 0.f;

    const int nk = K / 32;
    auto loadAB = [&](int s, int k0) {
#pragma unroll
        for (int it = 0; it < 2 * MT; it++) {
            int lin = tid + it * 128;
            int r = lin >> 3, k4 = (lin & 7) * 4;
            cpa16(smb + (uint32_t)(s * ASZ + r * 36 + k4) * 4,
                  &A[(size_t)(row0 + r) * K + k0 + k4]);
        }
#pragma unroll
        for (int it = 0; it < 8; it++) {
            int lin = tid + it * 128;
            int r = lin >> 5, n4 = (lin & 31) * 4;
            cpa16(smb + (uint32_t)(BOFF + s * 4352 + r * 136 + n4) * 4,
                  &Bm[(size_t)(k0 + r) * N + col0 + n4]);
        }
        CP_COMMIT();
    };

    loadAB(0, 0);
    for (int kt = 0; kt < nk; kt++) {
        if (kt + 1 < nk) { loadAB((kt + 1) & 1, (kt + 1) * 32); CP_WAIT1(); }
        else             { CP_WAIT0(); }
        __syncthreads();
        const float* As = sm + (kt & 1) * ASZ;
        const float* Bs = sm + BOFF + (kt & 1) * 4352;
#pragma unroll
        for (int k8 = 0; k8 < 32; k8 += 8) {
            uint32_t a[MT][4], b[8][2];
#pragma unroll
            for (int mt = 0; mt < MT; mt++) {
                int r = wm * (MT * 16) + mt * 16 + lr;
                a[mt][0] = __float_as_uint(As[r * 36 + k8 + lc]);
                a[mt][1] = __float_as_uint(As[(r + 8) * 36 + k8 + lc]);
                a[mt][2] = __float_as_uint(As[r * 36 + k8 + lc + 4]);
                a[mt][3] = __float_as_uint(As[(r + 8) * 36 + k8 + lc + 4]);
            }
#pragma unroll
            for (int nt = 0; nt < 8; nt++) {
                int c = wn * 64 + nt * 8 + lr;
                b[nt][0] = __float_as_uint(Bs[(k8 + lc) * 136 + c]);
                b[nt][1] = __float_as_uint(Bs[(k8 + lc + 4) * 136 + c]);
            }
#pragma unroll
            for (int mt = 0; mt < MT; mt++)
#pragma unroll
                for (int nt = 0; nt < 8; nt++)
                    mma8(acc[mt][nt], a[mt], b[nt]);
        }
        __syncthreads();
    }

#pragma unroll
    for (int mt = 0; mt < MT; mt++)
#pragma unroll
        for (int nt = 0; nt < 8; nt++) {
            int r_ = row0 + wm * (MT * 16) + mt * 16 + lr;
            int c_ = col0 + wn * 64 + nt * 8 + 2 * lc;
#pragma unroll
            for (int hf = 0; hf < 2; hf++) {
                int rr = r_ + hf * 8;
                float v0 = acc[mt][nt][hf * 2 + 0];
                float v1 = acc[mt][nt][hf * 2 + 1];
                if (EPI == 0) {
                    if (bias) { v0 += bias[c_]; v1 += bias[c_ + 1]; }
                    if (ACT == 1) {
                        v0 = 0.5f * v0 * (1.0f + erff(v0 * 0.70710678118654752f));
                        v1 = 0.5f * v1 * (1.0f + erff(v1 * 0.70710678118654752f));
                    }
                    if (Res) {
                        v0 += Res[(size_t)rr * N + c_];
                        v1 += Res[(size_t)rr * N + c_ + 1];
                    }
                    if (RND) { v0 = rnd_tf(v0); v1 = rnd_tf(v1); }
                    C[(size_t)rr * N + c_]     = v0;
                    C[(size_t)rr * N + c_ + 1] = v1;
                } else if (EPI == 1) {
                    int b = rr >> 10, i = rr & 1023;
#pragma unroll
                    for (int e = 0; e < 2; e++) {
                        int cc = c_ + e;
                        int h = cc >> 6, d = cc & 63;
                        float val = e ? v1 : v0;
                        size_t dst = (((size_t)(b * Hc + h)) * Sc + i) * DHc + d;
                        C[dst] = rnd_tf(val + (bias ? bias[cc] : 0.f));
                        if (C2) C2[dst] = rnd_tf(val + bias2[cc]);
                    }
                } else { // EPI == 2
                    int b = rr / Sk, j = rr % Sk;
#pragma unroll
                    for (int e = 0; e < 2; e++) {
                        int cc = c_ + e;
                        int isv = cc >> 10;
                        int h = (cc & 1023) >> 6, d = cc & 63;
                        float val = e ? v1 : v0;
                        size_t dst = (((size_t)(b * Hc + h)) * Sk + j) * DHc + d;
                        (isv ? C2 : C)[dst] = rnd_tf(val);
                    }
                }
            }
        }
}

// ---------------- standalone GEMM kernel ----------------
template<int MT, int ACT, int EPI, int RND>
__global__ void __launch_bounds__(128, 4)
gemm_tf32(const float* __restrict__ A, const float* __restrict__ Bm,
          float* __restrict__ C, float* __restrict__ C2,
          int N, int K, const float* __restrict__ bias, const float* __restrict__ bias2,
          const float* __restrict__ Res, int Sk)
{
    extern __shared__ float sm[];
    gemm_body<MT, ACT, EPI, RND>(blockIdx.x, blockIdx.y, sm,
                                 A, Bm, C, C2, N, K, bias, bias2, Res, Sk);
}

// ---------------- merged dual GEMM: Q projection (EPI=1) + KV projection (EPI=2) --
// blocks [0, split): Q path (gx1 = 8 tiles wide). blocks [split, ...): KV path.
__global__ void __launch_bounds__(128, 4)
gemm_dual_qkv(const float* __restrict__ A1, const float* __restrict__ B1,
              float* __restrict__ C1, float* __restrict__ C1b,
              const float* __restrict__ ubias, const float* __restrict__ vbias,
              const float* __restrict__ A2, const float* __restrict__ B2,
              float* __restrict__ Ck, float* __restrict__ Cv,
              int N2, int Sk2, int split)
{
    extern __shared__ float sm[];
    if (blockIdx.x < (unsigned)split) {
        int id = blockIdx.x;
        gemm_body<2, 0, 1, 1>(id & 7, id >> 3, sm,
                              A1, B1, C1, C1b, Dc, Dc, ubias, vbias, nullptr, Sc);
    } else {
        int id = blockIdx.x - split;
        gemm_body<2, 0, 2, 1>(id & 15, id >> 4, sm,
                              A2, B2, Ck, Cv, N2, Dc, nullptr, nullptr, nullptr, Sk2);
    }
}

// ---------------- fused QK^T + shifted-pos + mask + column-max atomics ----------
template<int RELS>
__global__ void __launch_bounds__(256, 2)
qk_fused(const float* __restrict__ Q, const float* __restrict__ Q2,
         const float* __restrict__ Kk, const float* __restrict__ PE,
         float* __restrict__ Out, uint32_t* __restrict__ Mxu, int Srows, int Sk)
{
    extern __shared__ float sm[];
    const int tid = threadIdx.x, lane = tid & 31, wid = tid >> 5;
    const int wm = wid & 1, wn = wid >> 1;
    const int lr = lane >> 2, lc = lane & 3;
    const int z = blockIdx.z;
    const int j0 = blockIdx.x * 128, i0 = blockIdx.y * 128;
    const int bb = z >> 4, hh = z & 15;
    const uint32_t smb = (uint32_t)__cvta_generic_to_shared(sm);

    if (RELS && j0 > i0 + 127 + Mc) return;   // fully masked: never read downstream

    float acc[4][4][4];
#pragma unroll
    for (int mt = 0; mt < 4; mt++)
#pragma unroll
        for (int nt = 0; nt < 4; nt++)
#pragma unroll
            for (int e = 0; e < 4; e++) acc[mt][nt][e] = 0.f;

#pragma unroll
    for (int d0 = 0; d0 < DHc; d0 += 32) {
#pragma unroll
        for (int it = 0; it < 4; it++) {
            int lin = tid + it * 256;
            int r = lin >> 3, k4 = (lin & 7) * 4;
            cpa16(smb + (uint32_t)(r * 36 + k4) * 4,
                  &Q[((size_t)z * Srows + i0 + r) * DHc + d0 + k4]);
            cpa16(smb + (uint32_t)(4608 + r * 36 + k4) * 4,
                  &Kk[((size_t)z * Sk + j0 + r) * DHc + d0 + k4]);
            if (RELS) {
                int srcrow = i0 + r + (bb == 0 ? 1 : 0);
                int ok = srcrow < Srows;
                cpa16z(smb + (uint32_t)(9216 + r * 36 + k4) * 4,
                       &Q2[((size_t)z * Srows + (ok ? srcrow : 0)) * DHc + d0 + k4],
                       ok ? 16 : 0);
                cpa16(smb + (uint32_t)(13824 + r * 36 + k4) * 4,
                      &PE[(size_t)(j0 + r) * Dc + hh * DHc + d0 + k4]);
            }
        }
        CP_COMMIT();
        CP_WAIT0();
        __syncthreads();

        const float* Qs  = sm;
        const float* Ks  = sm + 4608;
        const float* Q2s = sm + 9216;
        const float* Ps  = sm + 13824;
#pragma unroll
        for (int k8 = 0; k8 < 32; k8 += 8) {
            uint32_t a[4][4], b[4][2];
#pragma unroll
            for (int mt = 0; mt < 4; mt++) {
                int r = wm * 64 + mt * 16 + lr;
                a[mt][0] = __float_as_uint(Qs[r * 36 + k8 + lc]);
                a[mt][1] = __float_as_uint(Qs[(r + 8) * 36 + k8 + lc]);
                a[mt][2] = __float_as_uint(Qs[r * 36 + k8 + lc + 4]);
                a[mt][3] = __float_as_uint(Qs[(r + 8) * 36 + k8 + lc + 4]);
            }
#pragma unroll
            for (int nt = 0; nt < 4; nt++) {
                int c = wn * 32 + nt * 8 + lr;
                b[nt][0] = __float_as_uint(Ks[c * 36 + k8 + lc]);
                b[nt][1] = __float_as_uint(Ks[c * 36 + k8 + lc + 4]);
            }
#pragma unroll
            for (int mt = 0; mt < 4; mt++)
#pragma unroll
                for (int nt = 0; nt < 4; nt++)
                    mma8(acc[mt][nt], a[mt], b[nt]);
            if (RELS) {
#pragma unroll
                for (int mt = 0; mt < 4; mt++) {
                    int r = wm * 64 + mt * 16 + lr;
                    a[mt][0] = __float_as_uint(Q2s[r * 36 + k8 + lc]);
                    a[mt][1] = __float_as_uint(Q2s[(r + 8) * 36 + k8 + lc]);
                    a[mt][2] = __float_as_uint(Q2s[r * 36 + k8 + lc + 4]);
                    a[mt][3] = __float_as_uint(Q2s[(r + 8) * 36 + k8 + lc + 4]);
                }
#pragma unroll
                for (int nt = 0; nt < 4; nt++) {
                    int c = wn * 32 + nt * 8 + lr;
                    b[nt][0] = __float_as_uint(Ps[c * 36 + k8 + lc]);
                    b[nt][1] = __float_as_uint(Ps[c * 36 + k8 + lc + 4]);
                }
#pragma unroll
                for (int mt = 0; mt < 4; mt++)
#pragma unroll
                    for (int nt = 0; nt < 4; nt++)
                        mma8(acc[mt][nt], a[mt], b[nt]);
            }
        }
        __syncthreads();
    }

    float cmax[4][2];
#pragma unroll
    for (int nt = 0; nt < 4; nt++) { cmax[nt][0] = -3.4e38f; cmax[nt][1] = -3.4e38f; }

#pragma unroll
    for (int mt = 0; mt < 4; mt++)
#pragma unroll
        for (int nt = 0; nt < 4; nt++) {
            int i_ = i0 + wm * 64 + mt * 16 + lr;
            int j_ = j0 + wn * 32 + nt * 8 + 2 * lc;
#pragma unroll
            for (int hf = 0; hf < 2; hf++) {
                int ii = i_ + hf * 8;
#pragma unroll
                for (int e = 0; e < 2; e++) {
                    int jj = j_ + e;
                    float val = acc[mt][nt][hf * 2 + e];
                    if (RELS && jj > ii + Mc) val = -1e30f;   // mask BEFORE scale
                    Out[((size_t)z * Srows + ii) * Sk + jj] = val;
                    cmax[nt][e] = fmaxf(cmax[nt][e], val);
                }
            }
        }

#pragma unroll
    for (int off = 4; off <= 16; off <<= 1)
#pragma unroll
        for (int nt = 0; nt < 4; nt++)
#pragma unroll
            for (int e = 0; e < 2; e++)
                cmax[nt][e] = fmaxf(cmax[nt][e],
                                    __shfl_xor_sync(0xffffffffu, cmax[nt][e], off));
    if (lane < 4) {
#pragma unroll
        for (int nt = 0; nt < 4; nt++)
#pragma unroll
            for (int e = 0; e < 2; e++) {
                int jj = j0 + wn * 32 + nt * 8 + 2 * lc + e;
                atomicMax(&Mxu[(size_t)z * Sk + jj], fkey(cmax[nt][e]));
            }
    }
}

// ---------------- colsumv: read-only column sum-of-exp, write msc + Vn ------------
template<int CAUS>
__global__ void colsumv(const float* __restrict__ P, const uint32_t* __restrict__ Mxu,
                        const float* __restrict__ V, float* __restrict__ Vn,
                        float* __restrict__ Msc, int Srows, int Sk)
{
    __shared__ float red[256];
    __shared__ float izs[128];
    const int z = blockIdx.y;
    const int jl = threadIdx.x & 127;
    const int ty = threadIdx.x >> 7;
    const int j0b = blockIdx.x * 128;
    const int j = j0b + jl;
    const float msc = funkey(Mxu[(size_t)z * Sk + j]) * 0.125f;
    const float* base = P + (size_t)z * Srows * Sk + j;
    const int zend = CAUS ? min(Srows, max(0, j - Mc)) : 0;
    const int i0s = zend + ((ty ^ zend) & 1);
    float s = 0.f;
#pragma unroll 4
    for (int i = i0s; i < Srows; i += 2)
        s += __expf(base[(size_t)i * Sk] * 0.125f - msc);
    red[threadIdx.x] = s;
    __syncthreads();
    if (ty == 0) {
        izs[jl] = 1.f / (red[jl] + red[jl + 128]);
        Msc[(size_t)z * Sk + j] = msc;
    }
    __syncthreads();
    for (int t = threadIdx.x; t < 128 * 16; t += 256) {
        int row = t >> 4, c4 = (t & 15) * 4;
        float iz = izs[row];
        size_t idx = ((size_t)z * Sk + j0b + row) * DHc + c4;
        float4 v = *(const float4*)&V[idx];
        float4 o = { rnd_tf(v.x * iz), rnd_tf(v.y * iz),
                     rnd_tf(v.z * iz), rnd_tf(v.w * iz) };
        *(float4*)&Vn[idx] = o;
    }
}

// ---------------- AV: on-the-fly exp of raw logits, 2-stage P / 2-stage V ---------
__global__ void __launch_bounds__(256, 2)
av_tf32(const float* __restrict__ P, const float* __restrict__ V,
        const float* __restrict__ Msc, float* __restrict__ O,
        int Srows, int Sk, int caus)
{
    extern __shared__ float sm[];
    const int tid = threadIdx.x, lane = tid & 31, wid = tid >> 5;
    const int wm = wid >> 1, wn = wid & 1;
    const int lr = lane >> 2, lc = lane & 3;
    const int z = blockIdx.y;
    const int i0 = blockIdx.x * 128;
    const int bb = z >> 4, hh = z & 15;
    const uint32_t smb = (uint32_t)__cvta_generic_to_shared(sm);

    float acc[2][4][4];
#pragma unroll
    for (int mt = 0; mt < 2; mt++)
#pragma unroll
        for (int nt = 0; nt < 4; nt++)
#pragma unroll
            for (int e = 0; e < 4; e++) acc[mt][nt][e] = 0.f;

    auto ldP = [&](int j0, float4* pr) {
#pragma unroll
        for (int it = 0; it < 4; it++) {
            int lin = tid + it * 256;
            int r = lin >> 3, jb = (lin & 7) * 4;
            pr[it] = *(const float4*)&P[((size_t)z * Srows + i0 + r) * Sk + j0 + jb];
        }
    };
    auto stP = [&](int s, const float4* pr, int j0) {
#pragma unroll
        for (int it = 0; it < 4; it++) {
            int lin = tid + it * 256;
            int r = lin >> 3, jb = (lin & 7) * 4;
            float4 m4 = *(const float4*)&Msc[(size_t)z * Sk + j0 + jb];
            float4 p;
            p.x = rnd_tf(__expf(pr[it].x * 0.125f - m4.x));
            p.y = rnd_tf(__expf(pr[it].y * 0.125f - m4.y));
            p.z = rnd_tf(__expf(pr[it].z * 0.125f - m4.z));
            p.w = rnd_tf(__expf(pr[it].w * 0.125f - m4.w));
            *(float4*)&sm[s * 4608 + r * 36 + jb] = p;
        }
    };
    auto ldV = [&](int s, int j0) {
#pragma unroll
        for (int it = 0; it < 2; it++) {
            int lin = tid + it * 256;
            int r = lin >> 4, n4 = (lin & 15) * 4;
            cpa16(smb + (uint32_t)(9216 + s * 2304 + r * 72 + n4) * 4,
                  &V[((size_t)z * Sk + j0 + r) * DHc + n4]);
        }
        CP_COMMIT();
    };

    int nk = Sk / 32;
    if (caus) nk = min(nk, (i0 + 127 + Mc) / 32 + 1);

    float4 pr[2][4];
    ldP(0, pr[0]);
    ldV(0, 0);
    if (nk > 1) { ldP(32, pr[1]); ldV(1, 32); }
    stP(0, pr[0], 0);
    if (nk > 1) { CP_WAIT1(); } else { CP_WAIT0(); }
    __syncthreads();

    for (int kt = 0; kt < nk; kt++) {
        const float* Ps = sm + (kt & 1) * 4608;
        const float* Vs = sm + 9216 + (kt & 1) * 2304;
#pragma unroll
        for (int k8 = 0; k8 < 32; k8 += 8) {
            uint32_t a[2][4], b[4][2];
#pragma unroll
            for (int mt = 0; mt < 2; mt++) {
                int r = wm * 32 + mt * 16 + lr;
                a[mt][0] = __float_as_uint(Ps[r * 36 + k8 + lc]);
                a[mt][1] = __float_as_uint(Ps[(r + 8) * 36 + k8 + lc]);
                a[mt][2] = __float_as_uint(Ps[r * 36 + k8 + lc + 4]);
                a[mt][3] = __float_as_uint(Ps[(r + 8) * 36 + k8 + lc + 4]);
            }
#pragma unroll
            for (int nt = 0; nt < 4; nt++) {
                int c = wn * 32 + nt * 8 + lr;
                b[nt][0] = __float_as_uint(Vs[(k8 + lc) * 72 + c]);
                b[nt][1] = __float_as_uint(Vs[(k8 + lc + 4) * 72 + c]);
            }
#pragma unroll
            for (int mt = 0; mt < 2; mt++)
#pragma unroll
                for (int nt = 0; nt < 4; nt++)
                    mma8(acc[mt][nt], a[mt], b[nt]);
        }
        if (kt + 1 < nk) {
            __syncthreads();
            stP((kt + 1) & 1, pr[(kt + 1) & 1], (kt + 1) * 32);
            if (kt + 2 < nk) {
                ldP((kt + 2) * 32, pr[kt & 1]);
                ldV(kt & 1, (kt + 2) * 32);
                CP_WAIT1();
            } else {
                CP_WAIT0();
            }
            __syncthreads();
        }
    }

#pragma unroll
    for (int mt = 0; mt < 2; mt++)
#pragma unroll
        for (int nt = 0; nt < 4; nt++) {
            int i_ = i0 + wm * 32 + mt * 16 + lr;
            int d_ = wn * 32 + nt * 8 + 2 * lc;
#pragma unroll
            for (int hf = 0; hf < 2; hf++) {
                int ii = i_ + hf * 8;
                size_t o = ((size_t)(bb * Sc) + ii) * Dc + hh * DHc + d_;
                O[o]     = rnd_tf(acc[mt][nt][hf * 2 + 0]);
                O[o + 1] = rnd_tf(acc[mt][nt][hf * 2 + 1]);
            }
        }
}

// ---------------- LayerNorm ----------------
__global__ void ln_kernel(const float* __restrict__ X, const float* __restrict__ gw,
                          const float* __restrict__ bw, float* __restrict__ Y,
                          float* __restrict__ Yr, float* __restrict__ Yr2,
                          const float* __restrict__ Res)
{
    __shared__ float s1[256], s2[256];
    const int row = blockIdx.x;
    const int tid = threadIdx.x;
    const float* x = X + (size_t)row * Dc;
    float4 v = *(const float4*)&x[tid * 4];
    s1[tid] = v.x + v.y + v.z + v.w;
    s2[tid] = v.x * v.x + v.y * v.y + v.z * v.z + v.w * v.w;
    __syncthreads();
    for (int st = 128; st > 0; st >>= 1) {
        if (tid < st) { s1[tid] += s1[tid + st]; s2[tid] += s2[tid + st]; }
        __syncthreads();
    }
    float mu = s1[0] * (1.f / Dc);
    float var = s2[0] * (1.f / Dc) - mu * mu;
    float rinv = rsqrtf(var + 1e-5f);
    float4 g4 = *(const float4*)&gw[tid * 4];
    float4 b4 = *(const float4*)&bw[tid * 4];
    float4 o;
    o.x = (v.x - mu) * rinv * g4.x + b4.x;
    o.y = (v.y - mu) * rinv * g4.y + b4.y;
    o.z = (v.z - mu) * rinv * g4.z + b4.z;
    o.w = (v.w - mu) * rinv * g4.w + b4.w;
    if (Res) {
        float4 r4 = *(const float4*)&Res[(size_t)row * Dc + tid * 4];
        o.x += r4.x; o.y += r4.y; o.z += r4.z; o.w += r4.w;
    }
    *(float4*)&Y[(size_t)row * Dc + tid * 4] = o;
    if (Yr || Yr2) {
        float4 r = { rnd_tf(o.x), rnd_tf(o.y), rnd_tf(o.z), rnd_tf(o.w) };
        if (Yr) *(float4*)&Yr[(size_t)row * Dc + tid * 4] = r;
        if (Yr2) {
            int b = row >> 10;
            *(float4*)&Yr2[((size_t)(row + (b + 1) * Mc)) * Dc + tid * 4] = r;
        }
    }
}

// ---------------- host-side launcher ----------------
static inline float* sym(const void* s)
{
    void* p = nullptr;
    cudaGetSymbolAddress(&p, s);
    return (float*)p;
}

extern "C" void kernel_launch(void* const* d_in, const int* in_sizes, int n_in,
                              void* d_out, int out_size)
{
    const float* x     = (const float*)d_in[0];
    const float* enc   = (const float*)d_in[1];
    const float* pemb  = (const float*)d_in[2];
    const float* u     = (const float*)d_in[3];
    const float* vvec  = (const float*)d_in[4];
    const float* mem   = (const float*)d_in[5];
    // d_in[6] = tgt_mask — recomputed analytically
    const float* Wq_m  = (const float*)d_in[7];
    const float* Wkv_m = (const float*)d_in[8];
    const float* fcw_m = (const float*)d_in[9];
    const float* fcb_m = (const float*)d_in[10];
    const float* lnm_g = (const float*)d_in[11];
    const float* lnm_b = (const float*)d_in[12];
    const float* Wq_c  = (const float*)d_in[13];
    const float* Wkv_c = (const float*)d_in[14];
    const float* fcw_c = (const float*)d_in[15];
    const float* fcb_c = (const float*)d_in[16];
    const float* lnc_g = (const float*)d_in[17];
    const float* lnc_b = (const float*)d_in[18];
    const float* W1    = (const float*)d_in[19];
    const float* b1    = (const float*)d_in[20];
    const float* W2    = (const float*)d_in[21];
    const float* b2    = (const float*)d_in[22];
    const float* ln1_g = (const float*)d_in[23];
    const float* ln1_b = (const float*)d_in[24];
    const float* ln2_g = (const float*)d_in[25];
    const float* ln2_b = (const float*)d_in[26];
    const float* ln3_g = (const float*)d_in[27];
    const float* ln3_b = (const float*)d_in[28];
    float* out = (float*)d_out;

    float* xn  = sym(g_xn);   float* xnr  = sym(g_xnr); float* hcat = sym(g_h);
    float* q   = sym(g_q);    float* q2   = sym(g_q2);
    float* kk  = sym(g_k);    float* vv   = sym(g_v);   float* vn = sym(g_vn);
    float* scs = sym(g_scb);  float* msc  = sym(g_msc);
    uint32_t* mxu  = (uint32_t*)sym(g_mxu);
    uint32_t* mxu2 = (uint32_t*)sym(g_mxu2);
    float* o   = sym(g_o);    float* tmp  = sym(g_tmp);
    float* o1  = sym(g_out);  float* o2   = sym(g_out2);
    float* ff  = sym(g_ff);   float* w    = sym(g_wts);

    float* wWq_m  = w + OFF_WQ_M;
    float* wWkv_m = w + OFF_WKV_M;
    float* wfcw_m = w + OFF_FCW_M;
    float* wWq_c  = w + OFF_WQ_C;
    float* wWkv_c = w + OFF_WKV_C;
    float* wfcw_c = w + OFF_FCW_C;
    float* wW1    = w + OFF_W1;
    float* wW2    = w + OFF_W2;
    float* wpemb  = w + OFF_PEMB;
    float* wenc   = w + OFF_ENC;

    const int GSM = 53248;   // 2-stage 64x128: 2*(64*36 + 32*136)*4 bytes
    cudaFuncSetAttribute(gemm_tf32<2,0,0,0>, cudaFuncAttributeMaxDynamicSharedMemorySize, GSM);
    cudaFuncSetAttribute(gemm_tf32<2,1,0,1>, cudaFuncAttributeMaxDynamicSharedMemorySize, GSM);
    cudaFuncSetAttribute(gemm_dual_qkv,      cudaFuncAttributeMaxDynamicSharedMemorySize, GSM);
    cudaFuncSetAttribute(qk_fused<1>, cudaFuncAttributeMaxDynamicSharedMemorySize, 73728);
    cudaFuncSetAttribute(qk_fused<0>, cudaFuncAttributeMaxDynamicSharedMemorySize, 73728);
    cudaFuncSetAttribute(av_tf32,     cudaFuncAttributeMaxDynamicSharedMemorySize, 55296);

    const int rowsBS = Bc * Sc;

    // ===== prep: merged pre-round + max-key init (one launch) =====
    round_all<<<22 * Q4 / 256 + 384, 256>>>(
        (const float4*)Wq_m, (const float4*)Wkv_m, (const float4*)fcw_m,
        (const float4*)Wq_c, (const float4*)Wkv_c, (const float4*)fcw_c,
        (const float4*)W1, (const float4*)W2, (const float4*)pemb,
        (const float4*)enc, (const float4*)mem, (float4*)w, (float4*)hcat,
        mxu, mxu2);

    // ===== pre-norm 1 (also fills hcat bottom half) =====
    ln_kernel<<<rowsBS, 256>>>(x, ln1_g, ln1_b, xn, xnr, hcat, nullptr);

    // ===== self MHA: merged Q + KV projection =====
    gemm_dual_qkv<<<256 + 1024, 128, GSM>>>(
        xnr, wWq_m, q, q2, u, vvec,
        hcat, wWkv_m, kk, vv, 2 * Dc, Stc, 256);

    qk_fused<1><<<dim3(16, 8, Zc), 256, 73728>>>(q, q2, kk, wpemb, scs, mxu, Sc, Stc);
    colsumv<1><<<dim3(Stc / 128, Zc), 256>>>(scs, mxu, vv, vn, msc, Sc, Stc);
    av_tf32<<<dim3(8, Zc), 256, 55296>>>(scs, vn, msc, o, Sc, Stc, 1);

    gemm_tf32<2,0,0,0><<<dim3(8, 32), 128, GSM>>>(o, wfcw_m, tmp, nullptr, Dc, Dc, fcb_m, nullptr, xn, 0);
    ln_kernel<<<rowsBS, 256>>>(tmp, lnm_g, lnm_b, o1, nullptr, nullptr, x);

    // ===== cross attention: merged Q + KV projection =====
    ln_kernel<<<rowsBS, 256>>>(o1, ln2_g, ln2_b, xn, xnr, nullptr, nullptr);
    gemm_dual_qkv<<<256 + 512, 128, GSM>>>(
        xnr, wWq_c, q, nullptr, nullptr, nullptr,
        wenc, wWkv_c, kk, vv, 2 * Dc, Sc, 256);

    qk_fused<0><<<dim3(8, 8, Zc), 256, 73728>>>(q, nullptr, kk, nullptr, scs, mxu2, Sc, Sc);
    colsumv<0><<<dim3(Sc / 128, Zc), 256>>>(scs, mxu2, vv, vn, msc, Sc, Sc);
    av_tf32<<<dim3(8, Zc), 256, 55296>>>(scs, vn, msc, o, Sc, Sc, 0);

    gemm_tf32<2,0,0,0><<<dim3(8, 32), 128, GSM>>>(o, wfcw_c, tmp, nullptr, Dc, Dc, fcb_c, nullptr, xn, 0);
    ln_kernel<<<rowsBS, 256>>>(tmp, lnc_g, lnc_b, o2, nullptr, nullptr, o1);

    // ===== FFN =====
    ln_kernel<<<rowsBS, 256>>>(o2, ln3_g, ln3_b, xn, xnr, nullptr, nullptr);
    gemm_tf32<2,1,0,1><<<dim3(32, 32), 128, GSM>>>(xnr, wW1, ff, nullptr, DFFc, Dc, b1, nullptr, nullptr, 0);
    gemm_tf32<2,0,0,0><<<dim3(8, 32), 128, GSM>>>(ff, wW2, out, nullptr, Dc, DFFc, b2, nullptr, o2, 0);
}